// round 4
// baseline (speedup 1.0000x reference)
#include <cuda_runtime.h>

// Problem constants (fixed by the dataset)
#define NN    50000
#define EE    800000
#define INDIM 64
#define HID   256
#define OUTD  128
#define C2    512   // 2*HID

// ---------------- device scratch (static: no allocation allowed) ----------------
__device__ float g_x3 [NN * C2];     // [N,512]  = concat(x1, x2)
__device__ float g_xc1[NN * HID];    // x @ w_conv1 (raw)
__device__ float g_xc2[NN * OUTD];   // x3 @ w_conv2 (raw)
__device__ float g_x7 [NN * OUTD];   // x5 then x5+x6
__device__ float g_xc3[NN];          // x7 @ w_conv3 (raw)
__device__ float g_pre[NN];          // x7 @ w_fc2 + b_fc2
__device__ float g_dis[NN];          // deg^-1/2 (0 if deg==0)
__device__ int   g_deg[NN];
__device__ int   g_colptr[NN + 1];
__device__ int   g_cursor[NN];
__device__ int   g_erow[EE];         // source row per CSR slot (sorted by dest col)
__device__ float g_ewt [EE];         // dis[row] per CSR slot
__device__ int   g_bsum[1024];
__device__ int   g_is64;

// ---------------- packed f32x2 helpers (FFMA2: 2x fp32 throughput) ----------------
__device__ __forceinline__ unsigned long long pk2(float x) {
    unsigned long long d;
    asm("mov.b64 %0, {%1, %1};" : "=l"(d) : "f"(x));
    return d;
}
__device__ __forceinline__ void fma2(unsigned long long& d, unsigned long long a,
                                     unsigned long long b) {
    asm("fma.rn.f32x2 %0, %1, %2, %0;" : "+l"(d) : "l"(a), "l"(b));
}
__device__ __forceinline__ void upk2(unsigned long long v, float& lo, float& hi) {
    asm("mov.b64 {%0, %1}, %2;" : "=f"(lo), "=f"(hi) : "l"(v));
}

// ---------------- edge dtype handling ----------------
// Reference declares edge_index as int64, but JAX without x64 emits int32.
// Detect: values are in [0, 50000) so if data is int64, every odd int32 word is 0.
__global__ void detect_kernel(const int* __restrict__ p, int nwords) {
    __shared__ int any;
    if (threadIdx.x == 0) any = 0;
    __syncthreads();
    int v = 0;
    for (int i = threadIdx.x; i < nwords; i += blockDim.x)
        if (i & 1) v |= p[i];
    if (v) atomicOr(&any, 1);
    __syncthreads();
    if (threadIdx.x == 0) g_is64 = (any == 0) ? 1 : 0;
}

__device__ __forceinline__ int edge_val(const void* e, long idx) {
    if (g_is64) return (int)((const long long*)e)[idx];
    return ((const int*)e)[idx];
}

// ---------------- CSR build ----------------
__global__ void zero_deg_kernel(int n) {
    int i = blockIdx.x * blockDim.x + threadIdx.x;
    if (i < n) g_deg[i] = 0;
}

__global__ void count_kernel(const void* __restrict__ edges, int E) {
    int e = blockIdx.x * blockDim.x + threadIdx.x;
    if (e < E) {
        int c = edge_val(edges, (long)E + e);
        atomicAdd(&g_deg[c], 1);
    }
}

#define SCB 512
__global__ void scan_blocks_kernel(int n) {
    __shared__ int sm[SCB];
    int i = blockIdx.x * SCB + threadIdx.x;
    int v = (i < n) ? g_deg[i] : 0;
    sm[threadIdx.x] = v;
    __syncthreads();
    for (int off = 1; off < SCB; off <<= 1) {
        int t = 0;
        if ((int)threadIdx.x >= off) t = sm[threadIdx.x - off];
        __syncthreads();
        sm[threadIdx.x] += t;
        __syncthreads();
    }
    if (i < n) g_colptr[i] = sm[threadIdx.x] - v;     // exclusive within block
    if (threadIdx.x == SCB - 1) g_bsum[blockIdx.x] = sm[SCB - 1];
}

__global__ void scan_sums_kernel(int nb) {
    __shared__ int sm[1024];
    int v = (threadIdx.x < (unsigned)nb) ? g_bsum[threadIdx.x] : 0;
    sm[threadIdx.x] = v;
    __syncthreads();
    for (int off = 1; off < 1024; off <<= 1) {
        int t = 0;
        if ((int)threadIdx.x >= off) t = sm[threadIdx.x - off];
        __syncthreads();
        sm[threadIdx.x] += t;
        __syncthreads();
    }
    if (threadIdx.x < (unsigned)nb) g_bsum[threadIdx.x] = sm[threadIdx.x] - v;  // exclusive
}

__global__ void scan_add_kernel(int n, int Etot) {
    int i = blockIdx.x * SCB + threadIdx.x;
    if (i < n) {
        int v = g_colptr[i] + g_bsum[blockIdx.x];
        g_colptr[i] = v;
        g_cursor[i] = v;
        int d = g_deg[i];
        g_dis[i] = (d > 0) ? rsqrtf((float)d) : 0.0f;
    }
    if (i == 0) g_colptr[n] = Etot;
}

__global__ void fill_kernel(const void* __restrict__ edges, int E) {
    int e = blockIdx.x * blockDim.x + threadIdx.x;
    if (e < E) {
        int r = edge_val(edges, e);
        int c = edge_val(edges, (long)E + e);
        int pos = atomicAdd(&g_cursor[c], 1);
        g_erow[pos] = r;
        g_ewt[pos]  = g_dis[r];
    }
}

// ================= GEMM 1: [N,64] @ [64, 512]  (f32x2 packed) =================
// y-blocks 0,1 -> fc (relu + b_fc -> g_x3[:, 0:256]);  y 2,3 -> raw -> g_xc1
// Block tile 128x128, 256 threads, 8x8 per thread (4 row-pairs x 8 cols).
// A staged k-major in SMEM (stride 130) so row pairs load as LDS.64 (f32x2).
__global__ __launch_bounds__(256) void gemm1_kernel(
    const float* __restrict__ x, const float* __restrict__ w_fc,
    const float* __restrict__ b_fc, const float* __restrict__ w_conv1, int n)
{
    __shared__ __align__(16) float As[32 * 130];
    __shared__ __align__(16) float Bs[32 * 128];
    int bm0 = blockIdx.x * 128;
    int bn0 = blockIdx.y * 128;
    bool isfc = (bn0 < 256);
    const float* Bb = isfc ? (w_fc + bn0) : (w_conv1 + (bn0 - 256));  // ldb = 256
    int tid = threadIdx.x, tx = tid & 15, ty = tid >> 4;

    unsigned long long acc[4][8];
    #pragma unroll
    for (int i = 0; i < 4; i++)
        #pragma unroll
        for (int c = 0; c < 8; c++) acc[i][c] = 0ull;

    for (int k0 = 0; k0 < 64; k0 += 32) {
        // stage A: 128 rows x 32 k, transposed to k-major
        #pragma unroll
        for (int i = 0; i < 4; i++) {
            int f = tid + i * 256;
            int r = f >> 3, c4 = f & 7;
            float4 v = make_float4(0.f, 0.f, 0.f, 0.f);
            int row = bm0 + r;
            if (row < n) v = ((const float4*)x)[row * 16 + (k0 >> 2) + c4];
            As[(c4 * 4 + 0) * 130 + r] = v.x;
            As[(c4 * 4 + 1) * 130 + r] = v.y;
            As[(c4 * 4 + 2) * 130 + r] = v.z;
            As[(c4 * 4 + 3) * 130 + r] = v.w;
        }
        // stage B: 32 k x 128 n (row-major)
        #pragma unroll
        for (int i = 0; i < 4; i++) {
            int f = tid + i * 256;
            int kr = f >> 5, c = f & 31;
            ((float4*)Bs)[kr * 32 + c] = ((const float4*)Bb)[(k0 + kr) * 64 + c];
        }
        __syncthreads();

        const unsigned long long* A64 = (const unsigned long long*)As;
        #pragma unroll
        for (int kk = 0; kk < 32; kk++) {
            unsigned long long a2[4];
            #pragma unroll
            for (int i = 0; i < 4; i++) a2[i] = A64[kk * 65 + ty * 4 + i];
            float4 b0 = *(const float4*)(Bs + kk * 128 + tx * 8);
            float4 b1 = *(const float4*)(Bs + kk * 128 + tx * 8 + 4);
            unsigned long long bb[8];
            bb[0] = pk2(b0.x); bb[1] = pk2(b0.y); bb[2] = pk2(b0.z); bb[3] = pk2(b0.w);
            bb[4] = pk2(b1.x); bb[5] = pk2(b1.y); bb[6] = pk2(b1.z); bb[7] = pk2(b1.w);
            #pragma unroll
            for (int i = 0; i < 4; i++)
                #pragma unroll
                for (int c = 0; c < 8; c++)
                    fma2(acc[i][c], a2[i], bb[c]);
        }
        __syncthreads();
    }

    // epilogue
    int colb = tx * 8;
    #pragma unroll
    for (int i = 0; i < 4; i++) {
        int r0 = bm0 + ty * 8 + 2 * i;
        float lo[8], hi[8];
        #pragma unroll
        for (int c = 0; c < 8; c++) upk2(acc[i][c], lo[c], hi[c]);
        if (isfc) {
            int col = bn0 + colb;
            float4 ba = *(const float4*)(b_fc + col);
            float4 bbv = *(const float4*)(b_fc + col + 4);
            if (r0 < n) {
                float4 o0 = make_float4(fmaxf(lo[0] + ba.x, 0.f), fmaxf(lo[1] + ba.y, 0.f),
                                        fmaxf(lo[2] + ba.z, 0.f), fmaxf(lo[3] + ba.w, 0.f));
                float4 o1 = make_float4(fmaxf(lo[4] + bbv.x, 0.f), fmaxf(lo[5] + bbv.y, 0.f),
                                        fmaxf(lo[6] + bbv.z, 0.f), fmaxf(lo[7] + bbv.w, 0.f));
                *(float4*)(g_x3 + (long)r0 * C2 + col)     = o0;
                *(float4*)(g_x3 + (long)r0 * C2 + col + 4) = o1;
            }
            if (r0 + 1 < n) {
                float4 o0 = make_float4(fmaxf(hi[0] + ba.x, 0.f), fmaxf(hi[1] + ba.y, 0.f),
                                        fmaxf(hi[2] + ba.z, 0.f), fmaxf(hi[3] + ba.w, 0.f));
                float4 o1 = make_float4(fmaxf(hi[4] + bbv.x, 0.f), fmaxf(hi[5] + bbv.y, 0.f),
                                        fmaxf(hi[6] + bbv.z, 0.f), fmaxf(hi[7] + bbv.w, 0.f));
                *(float4*)(g_x3 + (long)(r0 + 1) * C2 + col)     = o0;
                *(float4*)(g_x3 + (long)(r0 + 1) * C2 + col + 4) = o1;
            }
        } else {
            int col = (bn0 - 256) + colb;
            if (r0 < n) {
                *(float4*)(g_xc1 + (long)r0 * HID + col)     = make_float4(lo[0], lo[1], lo[2], lo[3]);
                *(float4*)(g_xc1 + (long)r0 * HID + col + 4) = make_float4(lo[4], lo[5], lo[6], lo[7]);
            }
            if (r0 + 1 < n) {
                *(float4*)(g_xc1 + (long)(r0 + 1) * HID + col)     = make_float4(hi[0], hi[1], hi[2], hi[3]);
                *(float4*)(g_xc1 + (long)(r0 + 1) * HID + col + 4) = make_float4(hi[4], hi[5], hi[6], hi[7]);
            }
        }
    }
}

// ---------------- Aggregate conv1: x3[:, 256:512] = relu(dis[i]*sum + b_conv1) ----------------
// float4 per thread: 64 threads per node, 2 nodes per 128-thread block.
__global__ __launch_bounds__(128) void agg1_kernel(const float* __restrict__ b_conv1, int n) {
    int node = blockIdx.x * 2 + (threadIdx.x >> 6);
    int f4 = threadIdx.x & 63;
    if (node >= n) return;
    int s = g_colptr[node], e = g_colptr[node + 1];
    float4 acc = make_float4(0.f, 0.f, 0.f, 0.f);
    for (int p = s; p < e; p++) {
        int r = g_erow[p];
        float w = g_ewt[p];
        float4 v = ((const float4*)g_xc1)[(long)r * 64 + f4];
        acc.x += w * v.x; acc.y += w * v.y; acc.z += w * v.z; acc.w += w * v.w;
    }
    float di = g_dis[node];
    float4 b = ((const float4*)b_conv1)[f4];
    float4 o = make_float4(fmaxf(acc.x * di + b.x, 0.f), fmaxf(acc.y * di + b.y, 0.f),
                           fmaxf(acc.z * di + b.z, 0.f), fmaxf(acc.w * di + b.w, 0.f));
    ((float4*)g_x3)[(long)node * 128 + 64 + f4] = o;
}

// ================= GEMM 2: [N,512] @ [512, 256]  (f32x2 packed) =================
// y-block 0 -> fc1 (relu + b_fc1 -> g_x7); y 1 -> raw -> g_xc2
__global__ __launch_bounds__(256) void gemm2_kernel(
    const float* __restrict__ w_fc1, const float* __restrict__ b_fc1,
    const float* __restrict__ w_conv2, int n)
{
    __shared__ __align__(16) float As[32 * 130];
    __shared__ __align__(16) float Bs[32 * 128];
    int bm0 = blockIdx.x * 128;
    int bn0 = blockIdx.y * 128;
    bool isfc = (bn0 < 128);
    const float* Bb = isfc ? w_fc1 : w_conv2;  // ldb = 128; full 128-col slab each
    const float* A = g_x3;
    int tid = threadIdx.x, tx = tid & 15, ty = tid >> 4;

    unsigned long long acc[4][8];
    #pragma unroll
    for (int i = 0; i < 4; i++)
        #pragma unroll
        for (int c = 0; c < 8; c++) acc[i][c] = 0ull;

    for (int k0 = 0; k0 < 512; k0 += 32) {
        #pragma unroll
        for (int i = 0; i < 4; i++) {
            int f = tid + i * 256;
            int r = f >> 3, c4 = f & 7;
            float4 v = make_float4(0.f, 0.f, 0.f, 0.f);
            int row = bm0 + r;
            if (row < n) v = ((const float4*)A)[(long)row * 128 + (k0 >> 2) + c4];
            As[(c4 * 4 + 0) * 130 + r] = v.x;
            As[(c4 * 4 + 1) * 130 + r] = v.y;
            As[(c4 * 4 + 2) * 130 + r] = v.z;
            As[(c4 * 4 + 3) * 130 + r] = v.w;
        }
        #pragma unroll
        for (int i = 0; i < 4; i++) {
            int f = tid + i * 256;
            int kr = f >> 5, c = f & 31;
            ((float4*)Bs)[kr * 32 + c] = ((const float4*)Bb)[(k0 + kr) * 32 + c];
        }
        __syncthreads();

        const unsigned long long* A64 = (const unsigned long long*)As;
        #pragma unroll
        for (int kk = 0; kk < 32; kk++) {
            unsigned long long a2[4];
            #pragma unroll
            for (int i = 0; i < 4; i++) a2[i] = A64[kk * 65 + ty * 4 + i];
            float4 b0 = *(const float4*)(Bs + kk * 128 + tx * 8);
            float4 b1 = *(const float4*)(Bs + kk * 128 + tx * 8 + 4);
            unsigned long long bb[8];
            bb[0] = pk2(b0.x); bb[1] = pk2(b0.y); bb[2] = pk2(b0.z); bb[3] = pk2(b0.w);
            bb[4] = pk2(b1.x); bb[5] = pk2(b1.y); bb[6] = pk2(b1.z); bb[7] = pk2(b1.w);
            #pragma unroll
            for (int i = 0; i < 4; i++)
                #pragma unroll
                for (int c = 0; c < 8; c++)
                    fma2(acc[i][c], a2[i], bb[c]);
        }
        __syncthreads();
    }

    int colb = tx * 8;
    #pragma unroll
    for (int i = 0; i < 4; i++) {
        int r0 = bm0 + ty * 8 + 2 * i;
        float lo[8], hi[8];
        #pragma unroll
        for (int c = 0; c < 8; c++) upk2(acc[i][c], lo[c], hi[c]);
        if (isfc) {
            int col = colb;
            float4 ba = *(const float4*)(b_fc1 + col);
            float4 bbv = *(const float4*)(b_fc1 + col + 4);
            if (r0 < n) {
                float4 o0 = make_float4(fmaxf(lo[0] + ba.x, 0.f), fmaxf(lo[1] + ba.y, 0.f),
                                        fmaxf(lo[2] + ba.z, 0.f), fmaxf(lo[3] + ba.w, 0.f));
                float4 o1 = make_float4(fmaxf(lo[4] + bbv.x, 0.f), fmaxf(lo[5] + bbv.y, 0.f),
                                        fmaxf(lo[6] + bbv.z, 0.f), fmaxf(lo[7] + bbv.w, 0.f));
                *(float4*)(g_x7 + (long)r0 * OUTD + col)     = o0;
                *(float4*)(g_x7 + (long)r0 * OUTD + col + 4) = o1;
            }
            if (r0 + 1 < n) {
                float4 o0 = make_float4(fmaxf(hi[0] + ba.x, 0.f), fmaxf(hi[1] + ba.y, 0.f),
                                        fmaxf(hi[2] + ba.z, 0.f), fmaxf(hi[3] + ba.w, 0.f));
                float4 o1 = make_float4(fmaxf(hi[4] + bbv.x, 0.f), fmaxf(hi[5] + bbv.y, 0.f),
                                        fmaxf(hi[6] + bbv.z, 0.f), fmaxf(hi[7] + bbv.w, 0.f));
                *(float4*)(g_x7 + (long)(r0 + 1) * OUTD + col)     = o0;
                *(float4*)(g_x7 + (long)(r0 + 1) * OUTD + col + 4) = o1;
            }
        } else {
            int col = colb;
            if (r0 < n) {
                *(float4*)(g_xc2 + (long)r0 * OUTD + col)     = make_float4(lo[0], lo[1], lo[2], lo[3]);
                *(float4*)(g_xc2 + (long)r0 * OUTD + col + 4) = make_float4(lo[4], lo[5], lo[6], lo[7]);
            }
            if (r0 + 1 < n) {
                *(float4*)(g_xc2 + (long)(r0 + 1) * OUTD + col)     = make_float4(hi[0], hi[1], hi[2], hi[3]);
                *(float4*)(g_xc2 + (long)(r0 + 1) * OUTD + col + 4) = make_float4(hi[4], hi[5], hi[6], hi[7]);
            }
        }
    }
}

// ---------------- Aggregate conv2: x7 += relu(dis[i]*sum + b_conv2) ----------------
// float4 per thread: 32 threads per node, 4 nodes per 128-thread block.
__global__ __launch_bounds__(128) void agg2_kernel(const float* __restrict__ b_conv2, int n) {
    int node = blockIdx.x * 4 + (threadIdx.x >> 5);
    int f4 = threadIdx.x & 31;
    if (node >= n) return;
    int s = g_colptr[node], e = g_colptr[node + 1];
    float4 acc = make_float4(0.f, 0.f, 0.f, 0.f);
    for (int p = s; p < e; p++) {
        int r = g_erow[p];
        float w = g_ewt[p];
        float4 v = ((const float4*)g_xc2)[(long)r * 32 + f4];
        acc.x += w * v.x; acc.y += w * v.y; acc.z += w * v.z; acc.w += w * v.w;
    }
    float di = g_dis[node];
    float4 b = ((const float4*)b_conv2)[f4];
    float4 cur = ((const float4*)g_x7)[(long)node * 32 + f4];
    cur.x += fmaxf(acc.x * di + b.x, 0.f);
    cur.y += fmaxf(acc.y * di + b.y, 0.f);
    cur.z += fmaxf(acc.z * di + b.z, 0.f);
    cur.w += fmaxf(acc.w * di + b.w, 0.f);
    ((float4*)g_x7)[(long)node * 32 + f4] = cur;
}

// ---------------- Head: per-node dots with w_fc2 / w_conv3 (warp per node) ----------------
__global__ __launch_bounds__(256) void head_kernel(
    const float* __restrict__ w_fc2, const float* __restrict__ b_fc2,
    const float* __restrict__ w_conv3, int n)
{
    int gw = (blockIdx.x * blockDim.x + threadIdx.x) >> 5;
    int lane = threadIdx.x & 31;
    if (gw >= n) return;
    float4 v  = ((const float4*)g_x7)[(long)gw * 32 + lane];
    float4 wf = ((const float4*)w_fc2)[lane];
    float4 wc = ((const float4*)w_conv3)[lane];
    float d1 = v.x * wf.x + v.y * wf.y + v.z * wf.z + v.w * wf.w;
    float d2 = v.x * wc.x + v.y * wc.y + v.z * wc.z + v.w * wc.w;
    #pragma unroll
    for (int off = 16; off > 0; off >>= 1) {
        d1 += __shfl_down_sync(0xffffffffu, d1, off);
        d2 += __shfl_down_sync(0xffffffffu, d2, off);
    }
    if (lane == 0) {
        g_pre[gw] = d1 + b_fc2[0];
        g_xc3[gw] = d2;
    }
}

// ---------------- Final aggregate conv3 + output ----------------
__global__ __launch_bounds__(256) void agg3_kernel(
    const float* __restrict__ b_conv3, float* __restrict__ out, int n)
{
    int gw = (blockIdx.x * blockDim.x + threadIdx.x) >> 5;
    int lane = threadIdx.x & 31;
    if (gw >= n) return;
    int s = g_colptr[gw], e = g_colptr[gw + 1];
    float acc = 0.f;
    for (int p = s + lane; p < e; p += 32)
        acc += g_ewt[p] * g_xc3[g_erow[p]];
    #pragma unroll
    for (int off = 16; off > 0; off >>= 1)
        acc += __shfl_down_sync(0xffffffffu, acc, off);
    if (lane == 0)
        out[gw] = g_pre[gw] + b_conv3[0] + g_dis[gw] * acc;
}

// ---------------- launch ----------------
extern "C" void kernel_launch(void* const* d_in, const int* in_sizes, int n_in,
                              void* d_out, int out_size)
{
    const float* x        = (const float*)d_in[0];
    const void*  edges    = d_in[1];
    const float* w_fc     = (const float*)d_in[2];
    const float* b_fc     = (const float*)d_in[3];
    const float* w_conv1  = (const float*)d_in[4];
    const float* b_conv1  = (const float*)d_in[5];
    const float* w_fc1    = (const float*)d_in[6];
    const float* b_fc1    = (const float*)d_in[7];
    const float* w_conv2  = (const float*)d_in[8];
    const float* b_conv2  = (const float*)d_in[9];
    const float* w_fc2    = (const float*)d_in[10];
    const float* b_fc2    = (const float*)d_in[11];
    const float* w_conv3  = (const float*)d_in[12];
    const float* b_conv3  = (const float*)d_in[13];
    float* out = (float*)d_out;

    int n = in_sizes[0] / INDIM;   // 50000
    int E = in_sizes[1] / 2;       // 800000

    int NB = (n + SCB - 1) / SCB;

    detect_kernel<<<1, 256>>>((const int*)edges, 4096);
    zero_deg_kernel<<<(n + 255) / 256, 256>>>(n);
    count_kernel<<<(E + 255) / 256, 256>>>(edges, E);
    scan_blocks_kernel<<<NB, SCB>>>(n);
    scan_sums_kernel<<<1, 1024>>>(NB);
    scan_add_kernel<<<NB, SCB>>>(n, E);
    fill_kernel<<<(E + 255) / 256, 256>>>(edges, E);

    dim3 g1((n + 127) / 128, 4);
    gemm1_kernel<<<g1, 256>>>(x, w_fc, b_fc, w_conv1, n);
    agg1_kernel<<<(n + 1) / 2, 128>>>(b_conv1, n);

    dim3 g2((n + 127) / 128, 2);
    gemm2_kernel<<<g2, 256>>>(w_fc1, b_fc1, w_conv2, n);
    agg2_kernel<<<(n + 3) / 4, 128>>>(b_conv2, n);

    int blocks = (n * 32 + 255) / 256;
    head_kernel<<<blocks, 256>>>(w_fc2, b_fc2, w_conv3, n);
    agg3_kernel<<<blocks, 256>>>(b_conv3, out, n);
}

// round 7
// speedup vs baseline: 2.6824x; 2.6824x over previous
#include <cuda_runtime.h>
#include <cuda_bf16.h>
#include <cstdint>

// Problem constants (fixed by the dataset)
#define NN    50000
#define EE    800000
#define INDIM 64
#define HID   256
#define OUTD  128
#define C2    512   // 2*HID

// ---------------- device scratch (static: no allocation allowed) ----------------
__device__ __nv_bfloat16 g_xh [NN * INDIM];   // x split hi
__device__ __nv_bfloat16 g_xl [NN * INDIM];   // x split lo
__device__ __nv_bfloat16 g_x3h[NN * C2];      // x3 split hi
__device__ __nv_bfloat16 g_x3l[NN * C2];      // x3 split lo
__device__ __nv_bfloat16 g_b1h[C2 * INDIM];   // B1[n][k] = concat(w_fc,w_conv1)^T hi
__device__ __nv_bfloat16 g_b1l[C2 * INDIM];
__device__ __nv_bfloat16 g_b2h[256 * C2];     // B2[n][k] = concat(w_fc1,w_conv2)^T hi
__device__ __nv_bfloat16 g_b2l[256 * C2];
__device__ float g_xc1[NN * HID];    // x @ w_conv1 (raw, fp32)
__device__ float g_xc2[NN * OUTD];   // x3 @ w_conv2 (raw, fp32)
__device__ float g_x7 [NN * OUTD];   // x5 then x5+x6
__device__ float g_xc3[NN];
__device__ float g_pre[NN];
__device__ float g_dis[NN];
__device__ int   g_deg[NN];
__device__ int   g_colptr[NN + 1];
__device__ int   g_cursor[NN];
__device__ int   g_erow[EE];
__device__ float g_ewt [EE];
__device__ int   g_bsum[1024];
__device__ int   g_is64;

// ---------------- mma.sync helpers (sm_80-era PTX: valid on plain sm_103) ----------------
__device__ __forceinline__ uint32_t smem_u32(const void* p) {
    uint32_t a;
    asm("{ .reg .u64 t; cvta.to.shared.u64 t, %1; cvt.u32.u64 %0, t; }" : "=r"(a) : "l"(p));
    return a;
}
__device__ __forceinline__ void ldsm4(uint32_t* d, uint32_t addr) {
    asm volatile("ldmatrix.sync.aligned.m8n8.x4.shared.b16 {%0,%1,%2,%3}, [%4];"
                 : "=r"(d[0]), "=r"(d[1]), "=r"(d[2]), "=r"(d[3]) : "r"(addr));
}
__device__ __forceinline__ void mma_bf16(float* c, const uint32_t* a, uint32_t b0, uint32_t b1) {
    asm volatile(
        "mma.sync.aligned.m16n8k16.row.col.f32.bf16.bf16.f32 "
        "{%0,%1,%2,%3}, {%4,%5,%6,%7}, {%8,%9}, {%0,%1,%2,%3};"
        : "+f"(c[0]), "+f"(c[1]), "+f"(c[2]), "+f"(c[3])
        : "r"(a[0]), "r"(a[1]), "r"(a[2]), "r"(a[3]), "r"(b0), "r"(b1));
}
__device__ __forceinline__ void fsplit(float v, __nv_bfloat16& h, __nv_bfloat16& l) {
    h = __float2bfloat16(v);
    l = __float2bfloat16(v - __bfloat162float(h));
}

// SMEM layout (both GEMMs): 128 rows x 64 bf16, stride 72 bf16 (144B, conflict-free ldmatrix)
#define LDS    72
#define TILEB  (128 * LDS * 2)     // 18432
#define G_AH   0
#define G_AL   TILEB
#define G_BH   (2 * TILEB)
#define G_BL   (3 * TILEB)
#define G_SMEM (4 * TILEB)         // 73728

// One K=64 chunk of the 3-product split GEMM. offA/offB are per-lane ldmatrix offsets.
__device__ __forceinline__ void chunk64(uint32_t sb, uint32_t offA, uint32_t offB,
                                        float acc[4][4][4]) {
    #pragma unroll
    for (int ks = 0; ks < 4; ks++) {
        uint32_t ka = ks * 32;                      // k16 step = 16 bf16 = 32 bytes
        uint32_t ah[4][4], al[4][4], bh[4][2], bl[4][2];
        #pragma unroll
        for (int mi = 0; mi < 4; mi++) ldsm4(ah[mi], sb + G_AH + offA + mi * 2304 + ka);
        #pragma unroll
        for (int mi = 0; mi < 4; mi++) ldsm4(al[mi], sb + G_AL + offA + mi * 2304 + ka);
        #pragma unroll
        for (int nj = 0; nj < 2; nj++) {
            uint32_t t[4];
            ldsm4(t, sb + G_BH + offB + nj * 2304 + ka);
            bh[nj * 2][0] = t[0]; bh[nj * 2][1] = t[1];
            bh[nj * 2 + 1][0] = t[2]; bh[nj * 2 + 1][1] = t[3];
            ldsm4(t, sb + G_BL + offB + nj * 2304 + ka);
            bl[nj * 2][0] = t[0]; bl[nj * 2][1] = t[1];
            bl[nj * 2 + 1][0] = t[2]; bl[nj * 2 + 1][1] = t[3];
        }
        #pragma unroll
        for (int mi = 0; mi < 4; mi++)
            #pragma unroll
            for (int nf = 0; nf < 4; nf++) {
                mma_bf16(acc[mi][nf], ah[mi], bh[nf][0], bh[nf][1]);
                mma_bf16(acc[mi][nf], ah[mi], bl[nf][0], bl[nf][1]);
                mma_bf16(acc[mi][nf], al[mi], bh[nf][0], bh[nf][1]);
            }
    }
}

// ---------------- edge dtype handling ----------------
__global__ void detect_kernel(const int* __restrict__ p, int nwords) {
    __shared__ int any;
    if (threadIdx.x == 0) any = 0;
    __syncthreads();
    int v = 0;
    for (int i = threadIdx.x; i < nwords; i += blockDim.x)
        if (i & 1) v |= p[i];
    if (v) atomicOr(&any, 1);
    __syncthreads();
    if (threadIdx.x == 0) g_is64 = (any == 0) ? 1 : 0;
}
__device__ __forceinline__ int edge_val(const void* e, long idx) {
    if (g_is64) return (int)((const long long*)e)[idx];
    return ((const int*)e)[idx];
}

// ---------------- CSR build ----------------
__global__ void zero_deg_kernel(int n) {
    int i = blockIdx.x * blockDim.x + threadIdx.x;
    if (i < n) g_deg[i] = 0;
}
__global__ void count_kernel(const void* __restrict__ edges, int E) {
    int e = blockIdx.x * blockDim.x + threadIdx.x;
    if (e < E) atomicAdd(&g_deg[edge_val(edges, (long)E + e)], 1);
}
#define SCB 512
__global__ void scan_blocks_kernel(int n) {
    __shared__ int sm[SCB];
    int i = blockIdx.x * SCB + threadIdx.x;
    int v = (i < n) ? g_deg[i] : 0;
    sm[threadIdx.x] = v;
    __syncthreads();
    for (int off = 1; off < SCB; off <<= 1) {
        int t = 0;
        if ((int)threadIdx.x >= off) t = sm[threadIdx.x - off];
        __syncthreads();
        sm[threadIdx.x] += t;
        __syncthreads();
    }
    if (i < n) g_colptr[i] = sm[threadIdx.x] - v;
    if (threadIdx.x == SCB - 1) g_bsum[blockIdx.x] = sm[SCB - 1];
}
__global__ void scan_sums_kernel(int nb) {
    __shared__ int sm[1024];
    int v = (threadIdx.x < (unsigned)nb) ? g_bsum[threadIdx.x] : 0;
    sm[threadIdx.x] = v;
    __syncthreads();
    for (int off = 1; off < 1024; off <<= 1) {
        int t = 0;
        if ((int)threadIdx.x >= off) t = sm[threadIdx.x - off];
        __syncthreads();
        sm[threadIdx.x] += t;
        __syncthreads();
    }
    if (threadIdx.x < (unsigned)nb) g_bsum[threadIdx.x] = sm[threadIdx.x] - v;
}
__global__ void scan_add_kernel(int n, int Etot) {
    int i = blockIdx.x * SCB + threadIdx.x;
    if (i < n) {
        int v = g_colptr[i] + g_bsum[blockIdx.x];
        g_colptr[i] = v;
        g_cursor[i] = v;
        int d = g_deg[i];
        g_dis[i] = (d > 0) ? rsqrtf((float)d) : 0.0f;
    }
    if (i == 0) g_colptr[n] = Etot;
}
__global__ void fill_kernel(const void* __restrict__ edges, int E) {
    int e = blockIdx.x * blockDim.x + threadIdx.x;
    if (e < E) {
        int r = edge_val(edges, e);
        int c = edge_val(edges, (long)E + e);
        int pos = atomicAdd(&g_cursor[c], 1);
        g_erow[pos] = r;
        g_ewt[pos]  = g_dis[r];
    }
}

// ---------------- conversions ----------------
__global__ void conv_x_kernel(const float* __restrict__ x, int total) {
    int i = blockIdx.x * blockDim.x + threadIdx.x;
    if (i < total) fsplit(x[i], g_xh[i], g_xl[i]);
}
// B1[n][k] = (n<256 ? w_fc[k][n] : w_conv1[k][n-256]),  [512 x 64]
__global__ void conv_w1_kernel(const float* __restrict__ w_fc, const float* __restrict__ w_conv1) {
    int i = blockIdx.x * blockDim.x + threadIdx.x;   // 512*64
    int nidx = i >> 6, k = i & 63;
    float v = (nidx < 256) ? w_fc[k * 256 + nidx] : w_conv1[k * 256 + (nidx - 256)];
    fsplit(v, g_b1h[i], g_b1l[i]);
}
// B2[n][k] = (n<128 ? w_fc1[k][n] : w_conv2[k][n-128]),  [256 x 512]
__global__ void conv_w2_kernel(const float* __restrict__ w_fc1, const float* __restrict__ w_conv2) {
    int i = blockIdx.x * blockDim.x + threadIdx.x;   // 256*512
    int nidx = i >> 9, k = i & 511;
    float v = (nidx < 128) ? w_fc1[k * 128 + nidx] : w_conv2[k * 128 + (nidx - 128)];
    fsplit(v, g_b2h[i], g_b2l[i]);
}

// ================= GEMM1 (HMMA): [N,64] @ [64,512] =================
// y-blocks 0,1 (cols 0..255)  -> relu(+b_fc) -> x3 hi/lo bf16 split
// y-blocks 2,3 (cols 256..511)-> raw fp32    -> g_xc1
__global__ __launch_bounds__(256) void gemm1_mma(const float* __restrict__ b_fc, int n) {
    extern __shared__ char smem[];
    uint32_t sb = smem_u32(smem);
    int tid = threadIdx.x, wid = tid >> 5, lane = tid & 31;
    int bm0 = blockIdx.x * 128, bn0 = blockIdx.y * 128;
    bool isfc = bn0 < 256;
    int wm = (wid >> 2) * 64, wn = (wid & 3) * 32;

    // tile loads: A (x hi/lo), B (w1 hi/lo); 128 rows x 64 bf16 each
    #pragma unroll
    for (int i = 0; i < 4; i++) {
        int t = tid + i * 256;
        int row = t >> 3, j = t & 7;
        long grow = bm0 + row;
        uint4 vh = make_uint4(0u, 0u, 0u, 0u), vl = vh;
        if (grow < n) {
            vh = ((const uint4*)(g_xh + grow * 64))[j];
            vl = ((const uint4*)(g_xl + grow * 64))[j];
        }
        *(uint4*)(smem + G_AH + row * 144 + j * 16) = vh;
        *(uint4*)(smem + G_AL + row * 144 + j * 16) = vl;
        long rb = bn0 + row;
        *(uint4*)(smem + G_BH + row * 144 + j * 16) = ((const uint4*)(g_b1h + rb * 64))[j];
        *(uint4*)(smem + G_BL + row * 144 + j * 16) = ((const uint4*)(g_b1l + rb * 64))[j];
    }
    __syncthreads();

    int g = lane >> 3, r = lane & 7;
    uint32_t offA = (uint32_t)(((wm + (g & 1) * 8 + r) * LDS + (g >> 1) * 8) * 2);
    uint32_t offB = (uint32_t)(((wn + (g >> 1) * 8 + r) * LDS + (g & 1) * 8) * 2);

    float acc[4][4][4];
    #pragma unroll
    for (int mi = 0; mi < 4; mi++)
        #pragma unroll
        for (int nf = 0; nf < 4; nf++)
            #pragma unroll
            for (int q = 0; q < 4; q++) acc[mi][nf][q] = 0.f;

    chunk64(sb, offA, offB, acc);

    // epilogue
    int qrow = lane >> 2, qcol = (lane & 3) * 2;
    #pragma unroll
    for (int mi = 0; mi < 4; mi++) {
        int r0 = bm0 + wm + mi * 16 + qrow;
        int r1 = r0 + 8;
        #pragma unroll
        for (int nf = 0; nf < 4; nf++) {
            int col = bn0 + wn + nf * 8 + qcol;
            float* c = acc[mi][nf];
            if (isfc) {
                float2 bb = *(const float2*)(b_fc + col);
                if (r0 < n) {
                    float v0 = fmaxf(c[0] + bb.x, 0.f), v1 = fmaxf(c[1] + bb.y, 0.f);
                    __nv_bfloat16 h0, l0, h1, l1;
                    fsplit(v0, h0, l0); fsplit(v1, h1, l1);
                    __nv_bfloat162 th; th.x = h0; th.y = h1;
                    __nv_bfloat162 tl; tl.x = l0; tl.y = l1;
                    *(__nv_bfloat162*)(g_x3h + (long)r0 * C2 + col) = th;
                    *(__nv_bfloat162*)(g_x3l + (long)r0 * C2 + col) = tl;
                }
                if (r1 < n) {
                    float v0 = fmaxf(c[2] + bb.x, 0.f), v1 = fmaxf(c[3] + bb.y, 0.f);
                    __nv_bfloat16 h0, l0, h1, l1;
                    fsplit(v0, h0, l0); fsplit(v1, h1, l1);
                    __nv_bfloat162 th; th.x = h0; th.y = h1;
                    __nv_bfloat162 tl; tl.x = l0; tl.y = l1;
                    *(__nv_bfloat162*)(g_x3h + (long)r1 * C2 + col) = th;
                    *(__nv_bfloat162*)(g_x3l + (long)r1 * C2 + col) = tl;
                }
            } else {
                int cc = col - 256;
                if (r0 < n) *(float2*)(g_xc1 + (long)r0 * HID + cc) = make_float2(c[0], c[1]);
                if (r1 < n) *(float2*)(g_xc1 + (long)r1 * HID + cc) = make_float2(c[2], c[3]);
            }
        }
    }
}

// ---------------- Aggregate conv1: x3[:,256:512] = relu(dis*sum + b_conv1) -> bf16 split ----------------
__global__ __launch_bounds__(128) void agg1_kernel(const float* __restrict__ b_conv1, int n) {
    int node = blockIdx.x * 2 + (threadIdx.x >> 6);
    int f4 = threadIdx.x & 63;
    if (node >= n) return;
    int s = g_colptr[node], e = g_colptr[node + 1];
    float4 acc = make_float4(0.f, 0.f, 0.f, 0.f);
    for (int p = s; p < e; p++) {
        int r = g_erow[p];
        float w = g_ewt[p];
        float4 v = ((const float4*)g_xc1)[(long)r * 64 + f4];
        acc.x += w * v.x; acc.y += w * v.y; acc.z += w * v.z; acc.w += w * v.w;
    }
    float di = g_dis[node];
    float4 b = ((const float4*)b_conv1)[f4];
    float v0 = fmaxf(acc.x * di + b.x, 0.f);
    float v1 = fmaxf(acc.y * di + b.y, 0.f);
    float v2 = fmaxf(acc.z * di + b.z, 0.f);
    float v3 = fmaxf(acc.w * di + b.w, 0.f);
    __nv_bfloat16 h0, l0, h1, l1, h2, l2, h3, l3;
    fsplit(v0, h0, l0); fsplit(v1, h1, l1); fsplit(v2, h2, l2); fsplit(v3, h3, l3);
    long base = (long)node * C2 + 256 + f4 * 4;
    __nv_bfloat162 a2, b2;
    a2.x = h0; a2.y = h1; b2.x = h2; b2.y = h3;
    *(__nv_bfloat162*)(g_x3h + base)     = a2;
    *(__nv_bfloat162*)(g_x3h + base + 2) = b2;
    a2.x = l0; a2.y = l1; b2.x = l2; b2.y = l3;
    *(__nv_bfloat162*)(g_x3l + base)     = a2;
    *(__nv_bfloat162*)(g_x3l + base + 2) = b2;
}

// ================= GEMM2 (HMMA): [N,512] @ [512,256] =================
// y-block 0 (cols 0..127)  -> relu(+b_fc1) -> g_x7
// y-block 1 (cols 128..255)-> raw fp32     -> g_xc2
__global__ __launch_bounds__(256) void gemm2_mma(const float* __restrict__ b_fc1, int n) {
    extern __shared__ char smem[];
    uint32_t sb = smem_u32(smem);
    int tid = threadIdx.x, wid = tid >> 5, lane = tid & 31;
    int bm0 = blockIdx.x * 128, bn0 = blockIdx.y * 128;
    bool isfc = (bn0 == 0);
    int wm = (wid >> 2) * 64, wn = (wid & 3) * 32;

    int g = lane >> 3, r = lane & 7;
    uint32_t offA = (uint32_t)(((wm + (g & 1) * 8 + r) * LDS + (g >> 1) * 8) * 2);
    uint32_t offB = (uint32_t)(((wn + (g >> 1) * 8 + r) * LDS + (g & 1) * 8) * 2);

    float acc[4][4][4];
    #pragma unroll
    for (int mi = 0; mi < 4; mi++)
        #pragma unroll
        for (int nf = 0; nf < 4; nf++)
            #pragma unroll
            for (int q = 0; q < 4; q++) acc[mi][nf][q] = 0.f;

    for (int c = 0; c < 8; c++) {
        int k0 = c * 64;
        if (c) __syncthreads();
        #pragma unroll
        for (int i = 0; i < 4; i++) {
            int t = tid + i * 256;
            int row = t >> 3, j = t & 7;
            long grow = bm0 + row;
            uint4 vh = make_uint4(0u, 0u, 0u, 0u), vl = vh;
            if (grow < n) {
                vh = ((const uint4*)(g_x3h + grow * C2 + k0))[j];
                vl = ((const uint4*)(g_x3l + grow * C2 + k0))[j];
            }
            *(uint4*)(smem + G_AH + row * 144 + j * 16) = vh;
            *(uint4*)(smem + G_AL + row * 144 + j * 16) = vl;
            long rb = bn0 + row;
            *(uint4*)(smem + G_BH + row * 144 + j * 16) = ((const uint4*)(g_b2h + rb * C2 + k0))[j];
            *(uint4*)(smem + G_BL + row * 144 + j * 16) = ((const uint4*)(g_b2l + rb * C2 + k0))[j];
        }
        __syncthreads();
        chunk64(sb, offA, offB, acc);
    }

    int qrow = lane >> 2, qcol = (lane & 3) * 2;
    #pragma unroll
    for (int mi = 0; mi < 4; mi++) {
        int r0 = bm0 + wm + mi * 16 + qrow;
        int r1 = r0 + 8;
        #pragma unroll
        for (int nf = 0; nf < 4; nf++) {
            int col = wn + nf * 8 + qcol;     // 0..127 within slab
            float* c = acc[mi][nf];
            if (isfc) {
                float2 bb = *(const float2*)(b_fc1 + col);
                if (r0 < n) {
                    float2 o = make_float2(fmaxf(c[0] + bb.x, 0.f), fmaxf(c[1] + bb.y, 0.f));
                    *(float2*)(g_x7 + (long)r0 * OUTD + col) = o;
                }
                if (r1 < n) {
                    float2 o = make_float2(fmaxf(c[2] + bb.x, 0.f), fmaxf(c[3] + bb.y, 0.f));
                    *(float2*)(g_x7 + (long)r1 * OUTD + col) = o;
                }
            } else {
                if (r0 < n) *(float2*)(g_xc2 + (long)r0 * OUTD + col) = make_float2(c[0], c[1]);
                if (r1 < n) *(float2*)(g_xc2 + (long)r1 * OUTD + col) = make_float2(c[2], c[3]);
            }
        }
    }
}

// ---------------- Aggregate conv2: x7 += relu(dis*sum + b_conv2) ----------------
__global__ __launch_bounds__(128) void agg2_kernel(const float* __restrict__ b_conv2, int n) {
    int node = blockIdx.x * 4 + (threadIdx.x >> 5);
    int f4 = threadIdx.x & 31;
    if (node >= n) return;
    int s = g_colptr[node], e = g_colptr[node + 1];
    float4 acc = make_float4(0.f, 0.f, 0.f, 0.f);
    for (int p = s; p < e; p++) {
        int r = g_erow[p];
        float w = g_ewt[p];
        float4 v = ((const float4*)g_xc2)[(long)r * 32 + f4];
        acc.x += w * v.x; acc.y += w * v.y; acc.z += w * v.z; acc.w += w * v.w;
    }
    float di = g_dis[node];
    float4 b = ((const float4*)b_conv2)[f4];
    float4 cur = ((const float4*)g_x7)[(long)node * 32 + f4];
    cur.x += fmaxf(acc.x * di + b.x, 0.f);
    cur.y += fmaxf(acc.y * di + b.y, 0.f);
    cur.z += fmaxf(acc.z * di + b.z, 0.f);
    cur.w += fmaxf(acc.w * di + b.w, 0.f);
    ((float4*)g_x7)[(long)node * 32 + f4] = cur;
}

// ---------------- Head: per-node dots with w_fc2 / w_conv3 (warp per node) ----------------
__global__ __launch_bounds__(256) void head_kernel(
    const float* __restrict__ w_fc2, const float* __restrict__ b_fc2,
    const float* __restrict__ w_conv3, int n)
{
    int gw = (blockIdx.x * blockDim.x + threadIdx.x) >> 5;
    int lane = threadIdx.x & 31;
    if (gw >= n) return;
    float4 v  = ((const float4*)g_x7)[(long)gw * 32 + lane];
    float4 wf = ((const float4*)w_fc2)[lane];
    float4 wc = ((const float4*)w_conv3)[lane];
    float d1 = v.x * wf.x + v.y * wf.y + v.z * wf.z + v.w * wf.w;
    float d2 = v.x * wc.x + v.y * wc.y + v.z * wc.z + v.w * wc.w;
    #pragma unroll
    for (int off = 16; off > 0; off >>= 1) {
        d1 += __shfl_down_sync(0xffffffffu, d1, off);
        d2 += __shfl_down_sync(0xffffffffu, d2, off);
    }
    if (lane == 0) {
        g_pre[gw] = d1 + b_fc2[0];
        g_xc3[gw] = d2;
    }
}

// ---------------- Final aggregate conv3 + output ----------------
__global__ __launch_bounds__(256) void agg3_kernel(
    const float* __restrict__ b_conv3, float* __restrict__ out, int n)
{
    int gw = (blockIdx.x * blockDim.x + threadIdx.x) >> 5;
    int lane = threadIdx.x & 31;
    if (gw >= n) return;
    int s = g_colptr[gw], e = g_colptr[gw + 1];
    float acc = 0.f;
    for (int p = s + lane; p < e; p += 32)
        acc += g_ewt[p] * g_xc3[g_erow[p]];
    #pragma unroll
    for (int off = 16; off > 0; off >>= 1)
        acc += __shfl_down_sync(0xffffffffu, acc, off);
    if (lane == 0)
        out[gw] = g_pre[gw] + b_conv3[0] + g_dis[gw] * acc;
}

// ---------------- launch ----------------
extern "C" void kernel_launch(void* const* d_in, const int* in_sizes, int n_in,
                              void* d_out, int out_size)
{
    const float* x        = (const float*)d_in[0];
    const void*  edges    = d_in[1];
    const float* w_fc     = (const float*)d_in[2];
    const float* b_fc     = (const float*)d_in[3];
    const float* w_conv1  = (const float*)d_in[4];
    const float* b_conv1  = (const float*)d_in[5];
    const float* w_fc1    = (const float*)d_in[6];
    const float* b_fc1    = (const float*)d_in[7];
    const float* w_conv2  = (const float*)d_in[8];
    const float* b_conv2  = (const float*)d_in[9];
    const float* w_fc2    = (const float*)d_in[10];
    const float* b_fc2    = (const float*)d_in[11];
    const float* w_conv3  = (const float*)d_in[12];
    const float* b_conv3  = (const float*)d_in[13];
    float* out = (float*)d_out;

    int n = in_sizes[0] / INDIM;   // 50000
    int E = in_sizes[1] / 2;       // 800000
    int NB = (n + SCB - 1) / SCB;

    cudaFuncSetAttribute(gemm1_mma, cudaFuncAttributeMaxDynamicSharedMemorySize, G_SMEM);
    cudaFuncSetAttribute(gemm2_mma, cudaFuncAttributeMaxDynamicSharedMemorySize, G_SMEM);

    detect_kernel<<<1, 256>>>((const int*)edges, 4096);
    zero_deg_kernel<<<(n + 255) / 256, 256>>>(n);
    count_kernel<<<(E + 255) / 256, 256>>>(edges, E);
    scan_blocks_kernel<<<NB, SCB>>>(n);
    scan_sums_kernel<<<1, 1024>>>(NB);
    scan_add_kernel<<<NB, SCB>>>(n, E);
    fill_kernel<<<(E + 255) / 256, 256>>>(edges, E);

    conv_x_kernel<<<(n * INDIM + 255) / 256, 256>>>(x, n * INDIM);
    conv_w1_kernel<<<(C2 * INDIM) / 256, 256>>>(w_fc, w_conv1);
    conv_w2_kernel<<<(256 * C2) / 256, 256>>>(w_fc1, w_conv2);

    int mtiles = (n + 127) / 128;
    dim3 g1(mtiles, 4);
    gemm1_mma<<<g1, 256, G_SMEM>>>(b_fc, n);
    agg1_kernel<<<(n + 1) / 2, 128>>>(b_conv1, n);

    dim3 g2(mtiles, 2);
    gemm2_mma<<<g2, 256, G_SMEM>>>(b_fc1, n);
    agg2_kernel<<<(n + 3) / 4, 128>>>(b_conv2, n);

    int blocks = (n * 32 + 255) / 256;
    head_kernel<<<blocks, 256>>>(w_fc2, b_fc2, w_conv3, n);
    agg3_kernel<<<blocks, 256>>>(b_conv3, out, n);
}

// round 8
// speedup vs baseline: 2.7689x; 1.0323x over previous
#include <cuda_runtime.h>
#include <cuda_bf16.h>
#include <cstdint>

// Problem constants (fixed by the dataset)
#define NN    50000
#define EE    800000
#define INDIM 64
#define HID   256
#define OUTD  128
#define C2    512   // 2*HID

// ---------------- device scratch (static: no allocation allowed) ----------------
__device__ __nv_bfloat16 g_xh [NN * INDIM];   // x split hi
__device__ __nv_bfloat16 g_xl [NN * INDIM];   // x split lo
__device__ __nv_bfloat16 g_xah[NN * INDIM];   // (A_norm x) split hi
__device__ __nv_bfloat16 g_xal[NN * INDIM];   // (A_norm x) split lo
__device__ __nv_bfloat16 g_x3h[NN * C2];      // x3 split hi
__device__ __nv_bfloat16 g_x3l[NN * C2];      // x3 split lo
__device__ __nv_bfloat16 g_b1h[C2 * INDIM];   // B1[n][k] = concat(w_fc,w_conv1)^T hi
__device__ __nv_bfloat16 g_b1l[C2 * INDIM];
__device__ __nv_bfloat16 g_b2h[256 * C2];     // B2[n][k] = concat(w_fc1,w_conv2)^T hi
__device__ __nv_bfloat16 g_b2l[256 * C2];
__device__ float g_xc2[NN * OUTD];   // x3 @ w_conv2 (raw, fp32)
__device__ float g_x7 [NN * OUTD];   // x5 then x5+x6
__device__ float g_xc3[NN];
__device__ float g_pre[NN];
__device__ float g_dis[NN];
__device__ int   g_deg[NN];
__device__ int   g_colptr[NN + 1];
__device__ int   g_cursor[NN];
__device__ int   g_erow[EE];
__device__ float g_ewt [EE];
__device__ int   g_bsum[1024];
__device__ int   g_is64;

// ---------------- mma.sync helpers (sm_80-era PTX: valid on plain sm_103) ----------------
__device__ __forceinline__ uint32_t smem_u32(const void* p) {
    uint32_t a;
    asm("{ .reg .u64 t; cvta.to.shared.u64 t, %1; cvt.u32.u64 %0, t; }" : "=r"(a) : "l"(p));
    return a;
}
__device__ __forceinline__ void ldsm4(uint32_t* d, uint32_t addr) {
    asm volatile("ldmatrix.sync.aligned.m8n8.x4.shared.b16 {%0,%1,%2,%3}, [%4];"
                 : "=r"(d[0]), "=r"(d[1]), "=r"(d[2]), "=r"(d[3]) : "r"(addr));
}
__device__ __forceinline__ void mma_bf16(float* c, const uint32_t* a, uint32_t b0, uint32_t b1) {
    asm volatile(
        "mma.sync.aligned.m16n8k16.row.col.f32.bf16.bf16.f32 "
        "{%0,%1,%2,%3}, {%4,%5,%6,%7}, {%8,%9}, {%0,%1,%2,%3};"
        : "+f"(c[0]), "+f"(c[1]), "+f"(c[2]), "+f"(c[3])
        : "r"(a[0]), "r"(a[1]), "r"(a[2]), "r"(a[3]), "r"(b0), "r"(b1));
}
__device__ __forceinline__ void fsplit(float v, __nv_bfloat16& h, __nv_bfloat16& l) {
    h = __float2bfloat16(v);
    l = __float2bfloat16(v - __bfloat162float(h));
}
// cp.async 16B with zero-fill predicate (src-size 0 -> zeros)
__device__ __forceinline__ void cpa(uint32_t dst, const void* src, int pred) {
    asm volatile("cp.async.cg.shared.global [%0], [%1], 16, %2;"
                 :: "r"(dst), "l"(src), "r"(pred ? 16 : 0) : "memory");
}
#define CP_COMMIT() asm volatile("cp.async.commit_group;" ::: "memory")
#define CP_WAIT(N)  asm volatile("cp.async.wait_group %0;" :: "n"(N) : "memory")

// SMEM layout (both GEMMs): 128 rows x 64 bf16, stride 72 bf16 (144B, conflict-free ldmatrix)
#define LDS    72
#define TILEB  (128 * LDS * 2)     // 18432
#define G_AH   0
#define G_AL   TILEB
#define G_BH   (2 * TILEB)
#define G_BL   (3 * TILEB)
#define G_BUF  (4 * TILEB)         // 73728 per stage
#define G1_SMEM G_BUF
#define G2_SMEM (2 * G_BUF)        // 147456 (double buffered)

// One K=64 chunk of the 3-product split GEMM. base = smem addr of stage buffer.
__device__ __forceinline__ void chunk64(uint32_t base, uint32_t offA, uint32_t offB,
                                        float acc[4][4][4]) {
    #pragma unroll
    for (int ks = 0; ks < 4; ks++) {
        uint32_t ka = ks * 32;                      // k16 step = 16 bf16 = 32 bytes
        uint32_t ah[4][4], al[4][4], bh[4][2], bl[4][2];
        #pragma unroll
        for (int mi = 0; mi < 4; mi++) ldsm4(ah[mi], base + G_AH + offA + mi * 2304 + ka);
        #pragma unroll
        for (int mi = 0; mi < 4; mi++) ldsm4(al[mi], base + G_AL + offA + mi * 2304 + ka);
        #pragma unroll
        for (int nj = 0; nj < 2; nj++) {
            uint32_t t[4];
            ldsm4(t, base + G_BH + offB + nj * 2304 + ka);
            bh[nj * 2][0] = t[0]; bh[nj * 2][1] = t[1];
            bh[nj * 2 + 1][0] = t[2]; bh[nj * 2 + 1][1] = t[3];
            ldsm4(t, base + G_BL + offB + nj * 2304 + ka);
            bl[nj * 2][0] = t[0]; bl[nj * 2][1] = t[1];
            bl[nj * 2 + 1][0] = t[2]; bl[nj * 2 + 1][1] = t[3];
        }
        #pragma unroll
        for (int mi = 0; mi < 4; mi++)
            #pragma unroll
            for (int nf = 0; nf < 4; nf++) {
                mma_bf16(acc[mi][nf], ah[mi], bh[nf][0], bh[nf][1]);
                mma_bf16(acc[mi][nf], ah[mi], bl[nf][0], bl[nf][1]);
                mma_bf16(acc[mi][nf], al[mi], bh[nf][0], bh[nf][1]);
            }
    }
}

// ---------------- edge dtype handling ----------------
__global__ void detect_kernel(const int* __restrict__ p, int nwords) {
    __shared__ int any;
    if (threadIdx.x == 0) any = 0;
    __syncthreads();
    int v = 0;
    for (int i = threadIdx.x; i < nwords; i += blockDim.x)
        if (i & 1) v |= p[i];
    if (v) atomicOr(&any, 1);
    __syncthreads();
    if (threadIdx.x == 0) g_is64 = (any == 0) ? 1 : 0;
}
__device__ __forceinline__ int edge_val(const void* e, long idx) {
    if (g_is64) return (int)((const long long*)e)[idx];
    return ((const int*)e)[idx];
}

// ---------------- CSR build ----------------
__global__ void zero_deg_kernel(int n) {
    int i = blockIdx.x * blockDim.x + threadIdx.x;
    if (i < n) g_deg[i] = 0;
}
__global__ void count_kernel(const void* __restrict__ edges, int E) {
    int e = blockIdx.x * blockDim.x + threadIdx.x;
    if (e < E) atomicAdd(&g_deg[edge_val(edges, (long)E + e)], 1);
}
#define SCB 512
__global__ void scan_blocks_kernel(int n) {
    __shared__ int sm[SCB];
    int i = blockIdx.x * SCB + threadIdx.x;
    int v = (i < n) ? g_deg[i] : 0;
    sm[threadIdx.x] = v;
    __syncthreads();
    for (int off = 1; off < SCB; off <<= 1) {
        int t = 0;
        if ((int)threadIdx.x >= off) t = sm[threadIdx.x - off];
        __syncthreads();
        sm[threadIdx.x] += t;
        __syncthreads();
    }
    if (i < n) g_colptr[i] = sm[threadIdx.x] - v;
    if (threadIdx.x == SCB - 1) g_bsum[blockIdx.x] = sm[SCB - 1];
}
__global__ void scan_sums_kernel(int nb) {
    __shared__ int sm[1024];
    int v = (threadIdx.x < (unsigned)nb) ? g_bsum[threadIdx.x] : 0;
    sm[threadIdx.x] = v;
    __syncthreads();
    for (int off = 1; off < 1024; off <<= 1) {
        int t = 0;
        if ((int)threadIdx.x >= off) t = sm[threadIdx.x - off];
        __syncthreads();
        sm[threadIdx.x] += t;
        __syncthreads();
    }
    if (threadIdx.x < (unsigned)nb) g_bsum[threadIdx.x] = sm[threadIdx.x] - v;
}
__global__ void scan_add_kernel(int n, int Etot) {
    int i = blockIdx.x * SCB + threadIdx.x;
    if (i < n) {
        int v = g_colptr[i] + g_bsum[blockIdx.x];
        g_colptr[i] = v;
        g_cursor[i] = v;
        int d = g_deg[i];
        g_dis[i] = (d > 0) ? rsqrtf((float)d) : 0.0f;
    }
    if (i == 0) g_colptr[n] = Etot;
}
__global__ void fill_kernel(const void* __restrict__ edges, int E) {
    int e = blockIdx.x * blockDim.x + threadIdx.x;
    if (e < E) {
        int r = edge_val(edges, e);
        int c = edge_val(edges, (long)E + e);
        int pos = atomicAdd(&g_cursor[c], 1);
        g_erow[pos] = r;
        g_ewt[pos]  = g_dis[r];
    }
}

// ---------------- conversions ----------------
__global__ void conv_x_kernel(const float* __restrict__ x, int total) {
    int i = blockIdx.x * blockDim.x + threadIdx.x;
    if (i < total) fsplit(x[i], g_xh[i], g_xl[i]);
}
// B1[n][k] = (n<256 ? w_fc[k][n] : w_conv1[k][n-256]),  [512 x 64]
__global__ void conv_w1_kernel(const float* __restrict__ w_fc, const float* __restrict__ w_conv1) {
    int i = blockIdx.x * blockDim.x + threadIdx.x;   // 512*64
    int nidx = i >> 6, k = i & 63;
    float v = (nidx < 256) ? w_fc[k * 256 + nidx] : w_conv1[k * 256 + (nidx - 256)];
    fsplit(v, g_b1h[i], g_b1l[i]);
}
// B2[n][k] = (n<128 ? w_fc1[k][n] : w_conv2[k][n-128]),  [256 x 512]
__global__ void conv_w2_kernel(const float* __restrict__ w_fc1, const float* __restrict__ w_conv2) {
    int i = blockIdx.x * blockDim.x + threadIdx.x;   // 256*512
    int nidx = i >> 9, k = i & 511;
    float v = (nidx < 128) ? w_fc1[k * 128 + nidx] : w_conv2[k * 128 + (nidx - 128)];
    fsplit(v, g_b2h[i], g_b2l[i]);
}

// ---------------- Aggregate X (propagate-then-transform for conv1) ----------------
// xagg[i] = dis[i] * sum_e dis[row]*x[row]   (64-dim gather), split to bf16 hi/lo.
__global__ __launch_bounds__(128) void aggx_kernel(const float* __restrict__ x, int n) {
    int node = blockIdx.x * 8 + (threadIdx.x >> 4);
    int f4 = threadIdx.x & 15;
    if (node >= n) return;
    int s = g_colptr[node], e = g_colptr[node + 1];
    float4 acc = make_float4(0.f, 0.f, 0.f, 0.f);
    for (int p = s; p < e; p++) {
        int r = g_erow[p];
        float w = g_ewt[p];
        float4 v = ((const float4*)x)[(long)r * 16 + f4];
        acc.x += w * v.x; acc.y += w * v.y; acc.z += w * v.z; acc.w += w * v.w;
    }
    float di = g_dis[node];
    float v0 = acc.x * di, v1 = acc.y * di, v2 = acc.z * di, v3 = acc.w * di;
    __nv_bfloat16 h0, l0, h1, l1, h2, l2, h3, l3;
    fsplit(v0, h0, l0); fsplit(v1, h1, l1); fsplit(v2, h2, l2); fsplit(v3, h3, l3);
    long base = (long)node * 64 + f4 * 4;
    __nv_bfloat162 a2, b2;
    a2.x = h0; a2.y = h1; b2.x = h2; b2.y = h3;
    *(__nv_bfloat162*)(g_xah + base)     = a2;
    *(__nv_bfloat162*)(g_xah + base + 2) = b2;
    a2.x = l0; a2.y = l1; b2.x = l2; b2.y = l3;
    *(__nv_bfloat162*)(g_xal + base)     = a2;
    *(__nv_bfloat162*)(g_xal + base + 2) = b2;
}

// ================= GEMM1 (HMMA): [N,64] @ [64,512] -> x3 (all relu+bias, bf16 split) ========
// y 0,1 (cols 0..255):   A = x hi/lo,    bias b_fc     -> x1
// y 2,3 (cols 256..511): A = xagg hi/lo, bias b_conv1  -> x2 (conv1 via propagate-then-transform)
__global__ __launch_bounds__(256) void gemm1_mma(const float* __restrict__ b_fc,
                                                 const float* __restrict__ b_conv1, int n) {
    extern __shared__ char smem[];
    uint32_t sb = smem_u32(smem);
    int tid = threadIdx.x, wid = tid >> 5, lane = tid & 31;
    int bm0 = blockIdx.x * 128, bn0 = blockIdx.y * 128;
    bool isfc = bn0 < 256;
    const __nv_bfloat16* Ah = isfc ? g_xh : g_xah;
    const __nv_bfloat16* Al = isfc ? g_xl : g_xal;
    int wm = (wid >> 2) * 64, wn = (wid & 3) * 32;

    // tile loads: A hi/lo, B (w1 hi/lo); 128 rows x 64 bf16 each
    #pragma unroll
    for (int i = 0; i < 4; i++) {
        int t = tid + i * 256;
        int row = t >> 3, j = t & 7;
        long grow = bm0 + row;
        uint4 vh = make_uint4(0u, 0u, 0u, 0u), vl = vh;
        if (grow < n) {
            vh = ((const uint4*)(Ah + grow * 64))[j];
            vl = ((const uint4*)(Al + grow * 64))[j];
        }
        *(uint4*)(smem + G_AH + row * 144 + j * 16) = vh;
        *(uint4*)(smem + G_AL + row * 144 + j * 16) = vl;
        long rb = bn0 + row;
        *(uint4*)(smem + G_BH + row * 144 + j * 16) = ((const uint4*)(g_b1h + rb * 64))[j];
        *(uint4*)(smem + G_BL + row * 144 + j * 16) = ((const uint4*)(g_b1l + rb * 64))[j];
    }
    __syncthreads();

    int g = lane >> 3, r = lane & 7;
    uint32_t offA = (uint32_t)(((wm + (g & 1) * 8 + r) * LDS + (g >> 1) * 8) * 2);
    uint32_t offB = (uint32_t)(((wn + (g >> 1) * 8 + r) * LDS + (g & 1) * 8) * 2);

    float acc[4][4][4];
    #pragma unroll
    for (int mi = 0; mi < 4; mi++)
        #pragma unroll
        for (int nf = 0; nf < 4; nf++)
            #pragma unroll
            for (int q = 0; q < 4; q++) acc[mi][nf][q] = 0.f;

    chunk64(sb, offA, offB, acc);

    // epilogue: relu(v + bias) -> bf16 split into x3
    int qrow = lane >> 2, qcol = (lane & 3) * 2;
    #pragma unroll
    for (int mi = 0; mi < 4; mi++) {
        int r0 = bm0 + wm + mi * 16 + qrow;
        int r1 = r0 + 8;
        #pragma unroll
        for (int nf = 0; nf < 4; nf++) {
            int col = bn0 + wn + nf * 8 + qcol;
            float* c = acc[mi][nf];
            float2 bb = isfc ? *(const float2*)(b_fc + col)
                             : *(const float2*)(b_conv1 + (col - 256));
            if (r0 < n) {
                float v0 = fmaxf(c[0] + bb.x, 0.f), v1 = fmaxf(c[1] + bb.y, 0.f);
                __nv_bfloat16 h0, l0, h1, l1;
                fsplit(v0, h0, l0); fsplit(v1, h1, l1);
                __nv_bfloat162 th; th.x = h0; th.y = h1;
                __nv_bfloat162 tl; tl.x = l0; tl.y = l1;
                *(__nv_bfloat162*)(g_x3h + (long)r0 * C2 + col) = th;
                *(__nv_bfloat162*)(g_x3l + (long)r0 * C2 + col) = tl;
            }
            if (r1 < n) {
                float v0 = fmaxf(c[2] + bb.x, 0.f), v1 = fmaxf(c[3] + bb.y, 0.f);
                __nv_bfloat16 h0, l0, h1, l1;
                fsplit(v0, h0, l0); fsplit(v1, h1, l1);
                __nv_bfloat162 th; th.x = h0; th.y = h1;
                __nv_bfloat162 tl; tl.x = l0; tl.y = l1;
                *(__nv_bfloat162*)(g_x3h + (long)r1 * C2 + col) = th;
                *(__nv_bfloat162*)(g_x3l + (long)r1 * C2 + col) = tl;
            }
        }
    }
}

// ================= GEMM2 (HMMA, cp.async double-buffered): [N,512] @ [512,256] ========
// y-block 0 (cols 0..127)  -> relu(+b_fc1) -> g_x7
// y-block 1 (cols 128..255)-> raw fp32     -> g_xc2
__global__ __launch_bounds__(256) void gemm2_mma(const float* __restrict__ b_fc1, int n) {
    extern __shared__ char smem[];
    uint32_t sb = smem_u32(smem);
    int tid = threadIdx.x, wid = tid >> 5, lane = tid & 31;
    int bm0 = blockIdx.x * 128, bn0 = blockIdx.y * 128;
    bool isfc = (bn0 == 0);
    int wm = (wid >> 2) * 64, wn = (wid & 3) * 32;

    // per-thread load coordinates (4 quads per array)
    int rows[4], js[4];
    long garow[4];
    int apred[4];
    #pragma unroll
    for (int i = 0; i < 4; i++) {
        int t = tid + i * 256;
        rows[i] = t >> 3; js[i] = t & 7;
        long grow = bm0 + rows[i];
        apred[i] = grow < n;
        garow[i] = apred[i] ? grow : 0;
    }

    // issue one chunk's loads into stage buffer
    auto issue = [&](int c, int buf) {
        uint32_t base = sb + buf * G_BUF;
        int k0 = c * 64;
        #pragma unroll
        for (int i = 0; i < 4; i++) {
            int row = rows[i], j = js[i];
            uint32_t doff = row * 144 + j * 16;
            cpa(base + G_AH + doff, g_x3h + garow[i] * C2 + k0 + j * 8, apred[i]);
            cpa(base + G_AL + doff, g_x3l + garow[i] * C2 + k0 + j * 8, apred[i]);
            long rb = bn0 + row;
            cpa(base + G_BH + doff, g_b2h + rb * C2 + k0 + j * 8, 1);
            cpa(base + G_BL + doff, g_b2l + rb * C2 + k0 + j * 8, 1);
        }
        CP_COMMIT();
    };

    int g = lane >> 3, r = lane & 7;
    uint32_t offA = (uint32_t)(((wm + (g & 1) * 8 + r) * LDS + (g >> 1) * 8) * 2);
    uint32_t offB = (uint32_t)(((wn + (g >> 1) * 8 + r) * LDS + (g & 1) * 8) * 2);

    float acc[4][4][4];
    #pragma unroll
    for (int mi = 0; mi < 4; mi++)
        #pragma unroll
        for (int nf = 0; nf < 4; nf++)
            #pragma unroll
            for (int q = 0; q < 4; q++) acc[mi][nf][q] = 0.f;

    issue(0, 0);
    for (int c = 0; c < 8; c++) {
        if (c < 7) {
            issue(c + 1, (c + 1) & 1);
            CP_WAIT(1);
        } else {
            CP_WAIT(0);
        }
        __syncthreads();
        chunk64(sb + (c & 1) * G_BUF, offA, offB, acc);
        __syncthreads();
    }

    int qrow = lane >> 2, qcol = (lane & 3) * 2;
    #pragma unroll
    for (int mi = 0; mi < 4; mi++) {
        int r0 = bm0 + wm + mi * 16 + qrow;
        int r1 = r0 + 8;
        #pragma unroll
        for (int nf = 0; nf < 4; nf++) {
            int col = wn + nf * 8 + qcol;     // 0..127 within slab
            float* c = acc[mi][nf];
            if (isfc) {
                float2 bb = *(const float2*)(b_fc1 + col);
                if (r0 < n) {
                    float2 o = make_float2(fmaxf(c[0] + bb.x, 0.f), fmaxf(c[1] + bb.y, 0.f));
                    *(float2*)(g_x7 + (long)r0 * OUTD + col) = o;
                }
                if (r1 < n) {
                    float2 o = make_float2(fmaxf(c[2] + bb.x, 0.f), fmaxf(c[3] + bb.y, 0.f));
                    *(float2*)(g_x7 + (long)r1 * OUTD + col) = o;
                }
            } else {
                if (r0 < n) *(float2*)(g_xc2 + (long)r0 * OUTD + col) = make_float2(c[0], c[1]);
                if (r1 < n) *(float2*)(g_xc2 + (long)r1 * OUTD + col) = make_float2(c[2], c[3]);
            }
        }
    }
}

// ---------------- Aggregate conv2: x7 += relu(dis*sum + b_conv2) ----------------
__global__ __launch_bounds__(128) void agg2_kernel(const float* __restrict__ b_conv2, int n) {
    int node = blockIdx.x * 4 + (threadIdx.x >> 5);
    int f4 = threadIdx.x & 31;
    if (node >= n) return;
    int s = g_colptr[node], e = g_colptr[node + 1];
    float4 acc = make_float4(0.f, 0.f, 0.f, 0.f);
    for (int p = s; p < e; p++) {
        int r = g_erow[p];
        float w = g_ewt[p];
        float4 v = ((const float4*)g_xc2)[(long)r * 32 + f4];
        acc.x += w * v.x; acc.y += w * v.y; acc.z += w * v.z; acc.w += w * v.w;
    }
    float di = g_dis[node];
    float4 b = ((const float4*)b_conv2)[f4];
    float4 cur = ((const float4*)g_x7)[(long)node * 32 + f4];
    cur.x += fmaxf(acc.x * di + b.x, 0.f);
    cur.y += fmaxf(acc.y * di + b.y, 0.f);
    cur.z += fmaxf(acc.z * di + b.z, 0.f);
    cur.w += fmaxf(acc.w * di + b.w, 0.f);
    ((float4*)g_x7)[(long)node * 32 + f4] = cur;
}

// ---------------- Head: per-node dots with w_fc2 / w_conv3 (warp per node) ----------------
__global__ __launch_bounds__(256) void head_kernel(
    const float* __restrict__ w_fc2, const float* __restrict__ b_fc2,
    const float* __restrict__ w_conv3, int n)
{
    int gw = (blockIdx.x * blockDim.x + threadIdx.x) >> 5;
    int lane = threadIdx.x & 31;
    if (gw >= n) return;
    float4 v  = ((const float4*)g_x7)[(long)gw * 32 + lane];
    float4 wf = ((const float4*)w_fc2)[lane];
    float4 wc = ((const float4*)w_conv3)[lane];
    float d1 = v.x * wf.x + v.y * wf.y + v.z * wf.z + v.w * wf.w;
    float d2 = v.x * wc.x + v.y * wc.y + v.z * wc.z + v.w * wc.w;
    #pragma unroll
    for (int off = 16; off > 0; off >>= 1) {
        d1 += __shfl_down_sync(0xffffffffu, d1, off);
        d2 += __shfl_down_sync(0xffffffffu, d2, off);
    }
    if (lane == 0) {
        g_pre[gw] = d1 + b_fc2[0];
        g_xc3[gw] = d2;
    }
}

// ---------------- Final aggregate conv3 + output ----------------
__global__ __launch_bounds__(256) void agg3_kernel(
    const float* __restrict__ b_conv3, float* __restrict__ out, int n)
{
    int gw = (blockIdx.x * blockDim.x + threadIdx.x) >> 5;
    int lane = threadIdx.x & 31;
    if (gw >= n) return;
    int s = g_colptr[gw], e = g_colptr[gw + 1];
    float acc = 0.f;
    for (int p = s + lane; p < e; p += 32)
        acc += g_ewt[p] * g_xc3[g_erow[p]];
    #pragma unroll
    for (int off = 16; off > 0; off >>= 1)
        acc += __shfl_down_sync(0xffffffffu, acc, off);
    if (lane == 0)
        out[gw] = g_pre[gw] + b_conv3[0] + g_dis[gw] * acc;
}

// ---------------- launch ----------------
extern "C" void kernel_launch(void* const* d_in, const int* in_sizes, int n_in,
                              void* d_out, int out_size)
{
    const float* x        = (const float*)d_in[0];
    const void*  edges    = d_in[1];
    const float* w_fc     = (const float*)d_in[2];
    const float* b_fc     = (const float*)d_in[3];
    const float* w_conv1  = (const float*)d_in[4];
    const float* b_conv1  = (const float*)d_in[5];
    const float* w_fc1    = (const float*)d_in[6];
    const float* b_fc1    = (const float*)d_in[7];
    const float* w_conv2  = (const float*)d_in[8];
    const float* b_conv2  = (const float*)d_in[9];
    const float* w_fc2    = (const float*)d_in[10];
    const float* b_fc2    = (const float*)d_in[11];
    const float* w_conv3  = (const float*)d_in[12];
    const float* b_conv3  = (const float*)d_in[13];
    float* out = (float*)d_out;

    int n = in_sizes[0] / INDIM;   // 50000
    int E = in_sizes[1] / 2;       // 800000
    int NB = (n + SCB - 1) / SCB;

    cudaFuncSetAttribute(gemm1_mma, cudaFuncAttributeMaxDynamicSharedMemorySize, G1_SMEM);
    cudaFuncSetAttribute(gemm2_mma, cudaFuncAttributeMaxDynamicSharedMemorySize, G2_SMEM);

    detect_kernel<<<1, 256>>>((const int*)edges, 4096);
    zero_deg_kernel<<<(n + 255) / 256, 256>>>(n);
    count_kernel<<<(E + 255) / 256, 256>>>(edges, E);
    scan_blocks_kernel<<<NB, SCB>>>(n);
    scan_sums_kernel<<<1, 1024>>>(NB);
    scan_add_kernel<<<NB, SCB>>>(n, E);
    fill_kernel<<<(E + 255) / 256, 256>>>(edges, E);

    conv_x_kernel<<<(n * INDIM + 255) / 256, 256>>>(x, n * INDIM);
    conv_w1_kernel<<<(C2 * INDIM) / 256, 256>>>(w_fc, w_conv1);
    conv_w2_kernel<<<(256 * C2) / 256, 256>>>(w_fc1, w_conv2);

    aggx_kernel<<<(n + 7) / 8, 128>>>(x, n);

    int mtiles = (n + 127) / 128;
    dim3 g1(mtiles, 4);
    gemm1_mma<<<g1, 256, G1_SMEM>>>(b_fc, b_conv1, n);

    dim3 g2(mtiles, 2);
    gemm2_mma<<<g2, 256, G2_SMEM>>>(b_fc1, n);
    agg2_kernel<<<(n + 3) / 4, 128>>>(b_conv2, n);

    int blocks = (n * 32 + 255) / 256;
    head_kernel<<<blocks, 256>>>(w_fc2, b_fc2, w_conv3, n);
    agg3_kernel<<<blocks, 256>>>(b_conv3, out, n);
}

// round 9
// speedup vs baseline: 2.8769x; 1.0390x over previous
#include <cuda_runtime.h>
#include <cuda_bf16.h>
#include <cstdint>

// Problem constants (fixed by the dataset)
#define NN    50000
#define EE    800000
#define INDIM 64
#define HID   256
#define OUTD  128
#define C2    512   // 2*HID

// ---------------- device scratch (static: no allocation allowed) ----------------
__device__ __nv_bfloat16 g_xh [NN * INDIM];   // x split hi
__device__ __nv_bfloat16 g_xl [NN * INDIM];   // x split lo
__device__ __nv_bfloat16 g_xah[NN * INDIM];   // (A_norm x) split hi
__device__ __nv_bfloat16 g_xal[NN * INDIM];   // (A_norm x) split lo
__device__ __nv_bfloat16 g_x3h[NN * C2];      // x3 split hi
__device__ __nv_bfloat16 g_x3l[NN * C2];      // x3 split lo
__device__ __nv_bfloat16 g_b1h[C2 * INDIM];   // B1[n][k] = concat(w_fc,w_conv1)^T hi
__device__ __nv_bfloat16 g_b1l[C2 * INDIM];
__device__ __nv_bfloat16 g_b2h[256 * C2];     // B2[n][k] = concat(w_fc1,w_conv2)^T hi
__device__ __nv_bfloat16 g_b2l[256 * C2];
__device__ float g_xc2[NN * OUTD];   // x3 @ w_conv2 (raw, fp32)
__device__ float g_x7 [NN * OUTD];   // x5 (fc1 branch)
__device__ float g_xc3[NN];
__device__ float g_pre[NN];
__device__ float g_dis[NN];
__device__ int   g_deg[NN];
__device__ int   g_colptr[NN + 1];
__device__ int   g_cursor[NN];
__device__ int   g_erow[EE];
__device__ float g_ewt [EE];
__device__ int   g_bsum[1024];
__device__ int   g_is64;

// ---------------- mma.sync helpers (sm_80-era PTX: valid on plain sm_103) ----------------
__device__ __forceinline__ uint32_t smem_u32(const void* p) {
    uint32_t a;
    asm("{ .reg .u64 t; cvta.to.shared.u64 t, %1; cvt.u32.u64 %0, t; }" : "=r"(a) : "l"(p));
    return a;
}
__device__ __forceinline__ void ldsm4(uint32_t* d, uint32_t addr) {
    asm volatile("ldmatrix.sync.aligned.m8n8.x4.shared.b16 {%0,%1,%2,%3}, [%4];"
                 : "=r"(d[0]), "=r"(d[1]), "=r"(d[2]), "=r"(d[3]) : "r"(addr));
}
__device__ __forceinline__ void mma_bf16(float* c, const uint32_t* a, uint32_t b0, uint32_t b1) {
    asm volatile(
        "mma.sync.aligned.m16n8k16.row.col.f32.bf16.bf16.f32 "
        "{%0,%1,%2,%3}, {%4,%5,%6,%7}, {%8,%9}, {%0,%1,%2,%3};"
        : "+f"(c[0]), "+f"(c[1]), "+f"(c[2]), "+f"(c[3])
        : "r"(a[0]), "r"(a[1]), "r"(a[2]), "r"(a[3]), "r"(b0), "r"(b1));
}
__device__ __forceinline__ void fsplit(float v, __nv_bfloat16& h, __nv_bfloat16& l) {
    h = __float2bfloat16(v);
    l = __float2bfloat16(v - __bfloat162float(h));
}
// cp.async 16B with zero-fill predicate (src-size 0 -> zeros)
__device__ __forceinline__ void cpa(uint32_t dst, const void* src, int pred) {
    asm volatile("cp.async.cg.shared.global [%0], [%1], 16, %2;"
                 :: "r"(dst), "l"(src), "r"(pred ? 16 : 0) : "memory");
}
#define CP_COMMIT() asm volatile("cp.async.commit_group;" ::: "memory")
#define CP_WAIT(N)  asm volatile("cp.async.wait_group %0;" :: "n"(N) : "memory")

// SMEM layout (both GEMMs): 128 rows x 64 bf16, stride 72 bf16 (144B, conflict-free ldmatrix)
#define LDS    72
#define TILEB  (128 * LDS * 2)     // 18432
#define G_AH   0
#define G_AL   TILEB
#define G_BH   (2 * TILEB)
#define G_BL   (3 * TILEB)
#define G_BUF  (4 * TILEB)         // 73728 per stage
#define G1_SMEM G_BUF
#define G2_SMEM (2 * G_BUF)        // 147456 (double buffered)

// One K=64 chunk of the 3-product split GEMM. MF = #m-frags per warp.
template <int MF>
__device__ __forceinline__ void chunk64(uint32_t base, uint32_t offA, uint32_t offB,
                                        float acc[][4][4]) {
    #pragma unroll
    for (int ks = 0; ks < 4; ks++) {
        uint32_t ka = ks * 32;                      // k16 step = 16 bf16 = 32 bytes
        uint32_t ah[MF][4], al[MF][4], bh[4][2], bl[4][2];
        #pragma unroll
        for (int mi = 0; mi < MF; mi++) ldsm4(ah[mi], base + G_AH + offA + mi * 2304 + ka);
        #pragma unroll
        for (int mi = 0; mi < MF; mi++) ldsm4(al[mi], base + G_AL + offA + mi * 2304 + ka);
        #pragma unroll
        for (int nj = 0; nj < 2; nj++) {
            uint32_t t[4];
            ldsm4(t, base + G_BH + offB + nj * 2304 + ka);
            bh[nj * 2][0] = t[0]; bh[nj * 2][1] = t[1];
            bh[nj * 2 + 1][0] = t[2]; bh[nj * 2 + 1][1] = t[3];
            ldsm4(t, base + G_BL + offB + nj * 2304 + ka);
            bl[nj * 2][0] = t[0]; bl[nj * 2][1] = t[1];
            bl[nj * 2 + 1][0] = t[2]; bl[nj * 2 + 1][1] = t[3];
        }
        #pragma unroll
        for (int mi = 0; mi < MF; mi++)
            #pragma unroll
            for (int nf = 0; nf < 4; nf++) {
                mma_bf16(acc[mi][nf], ah[mi], bh[nf][0], bh[nf][1]);
                mma_bf16(acc[mi][nf], ah[mi], bl[nf][0], bl[nf][1]);
                mma_bf16(acc[mi][nf], al[mi], bh[nf][0], bh[nf][1]);
            }
    }
}

// ---------------- edge dtype handling ----------------
__global__ void detect_kernel(const int* __restrict__ p, int nwords) {
    __shared__ int any;
    if (threadIdx.x == 0) any = 0;
    __syncthreads();
    int v = 0;
    for (int i = threadIdx.x; i < nwords; i += blockDim.x)
        if (i & 1) v |= p[i];
    if (v) atomicOr(&any, 1);
    __syncthreads();
    if (threadIdx.x == 0) g_is64 = (any == 0) ? 1 : 0;
}
__device__ __forceinline__ int edge_val(const void* e, long idx) {
    if (g_is64) return (int)((const long long*)e)[idx];
    return ((const int*)e)[idx];
}

// ---------------- CSR build ----------------
__global__ void zero_deg_kernel(int n) {
    int i = blockIdx.x * blockDim.x + threadIdx.x;
    if (i < n) g_deg[i] = 0;
}
__global__ void count_kernel(const void* __restrict__ edges, int E) {
    int e = blockIdx.x * blockDim.x + threadIdx.x;
    if (e < E) atomicAdd(&g_deg[edge_val(edges, (long)E + e)], 1);
}
#define SCB 512
__global__ void scan_blocks_kernel(int n) {
    __shared__ int sm[SCB];
    int i = blockIdx.x * SCB + threadIdx.x;
    int v = (i < n) ? g_deg[i] : 0;
    sm[threadIdx.x] = v;
    __syncthreads();
    for (int off = 1; off < SCB; off <<= 1) {
        int t = 0;
        if ((int)threadIdx.x >= off) t = sm[threadIdx.x - off];
        __syncthreads();
        sm[threadIdx.x] += t;
        __syncthreads();
    }
    if (i < n) g_colptr[i] = sm[threadIdx.x] - v;
    if (threadIdx.x == SCB - 1) g_bsum[blockIdx.x] = sm[SCB - 1];
}
__global__ void scan_sums_kernel(int nb) {
    __shared__ int sm[1024];
    int v = (threadIdx.x < (unsigned)nb) ? g_bsum[threadIdx.x] : 0;
    sm[threadIdx.x] = v;
    __syncthreads();
    for (int off = 1; off < 1024; off <<= 1) {
        int t = 0;
        if ((int)threadIdx.x >= off) t = sm[threadIdx.x - off];
        __syncthreads();
        sm[threadIdx.x] += t;
        __syncthreads();
    }
    if (threadIdx.x < (unsigned)nb) g_bsum[threadIdx.x] = sm[threadIdx.x] - v;
}
__global__ void scan_add_kernel(int n, int Etot) {
    int i = blockIdx.x * SCB + threadIdx.x;
    if (i < n) {
        int v = g_colptr[i] + g_bsum[blockIdx.x];
        g_colptr[i] = v;
        g_cursor[i] = v;
        int d = g_deg[i];
        g_dis[i] = (d > 0) ? rsqrtf((float)d) : 0.0f;
    }
    if (i == 0) g_colptr[n] = Etot;
}
__global__ void fill_kernel(const void* __restrict__ edges, int E) {
    int e = blockIdx.x * blockDim.x + threadIdx.x;
    if (e < E) {
        int r = edge_val(edges, e);
        int c = edge_val(edges, (long)E + e);
        int pos = atomicAdd(&g_cursor[c], 1);
        g_erow[pos] = r;
        g_ewt[pos]  = g_dis[r];
    }
}

// ---------------- conversions ----------------
__global__ void conv_x_kernel(const float* __restrict__ x, int total) {
    int i = blockIdx.x * blockDim.x + threadIdx.x;
    if (i < total) fsplit(x[i], g_xh[i], g_xl[i]);
}
// B1[n][k] = (n<256 ? w_fc[k][n] : w_conv1[k][n-256]),  [512 x 64]
__global__ void conv_w1_kernel(const float* __restrict__ w_fc, const float* __restrict__ w_conv1) {
    int i = blockIdx.x * blockDim.x + threadIdx.x;   // 512*64
    int nidx = i >> 6, k = i & 63;
    float v = (nidx < 256) ? w_fc[k * 256 + nidx] : w_conv1[k * 256 + (nidx - 256)];
    fsplit(v, g_b1h[i], g_b1l[i]);
}
// B2[n][k] = (n<128 ? w_fc1[k][n] : w_conv2[k][n-128]),  [256 x 512]
__global__ void conv_w2_kernel(const float* __restrict__ w_fc1, const float* __restrict__ w_conv2) {
    int i = blockIdx.x * blockDim.x + threadIdx.x;   // 256*512
    int nidx = i >> 9, k = i & 511;
    float v = (nidx < 128) ? w_fc1[k * 128 + nidx] : w_conv2[k * 128 + (nidx - 128)];
    fsplit(v, g_b2h[i], g_b2l[i]);
}

// ---------------- Aggregate X (propagate-then-transform for conv1) ----------------
__global__ __launch_bounds__(128) void aggx_kernel(const float* __restrict__ x, int n) {
    int node = blockIdx.x * 8 + (threadIdx.x >> 4);
    int f4 = threadIdx.x & 15;
    if (node >= n) return;
    int s = g_colptr[node], e = g_colptr[node + 1];
    float4 acc = make_float4(0.f, 0.f, 0.f, 0.f);
    for (int p = s; p < e; p++) {
        int r = g_erow[p];
        float w = g_ewt[p];
        float4 v = ((const float4*)x)[(long)r * 16 + f4];
        acc.x += w * v.x; acc.y += w * v.y; acc.z += w * v.z; acc.w += w * v.w;
    }
    float di = g_dis[node];
    float v0 = acc.x * di, v1 = acc.y * di, v2 = acc.z * di, v3 = acc.w * di;
    __nv_bfloat16 h0, l0, h1, l1, h2, l2, h3, l3;
    fsplit(v0, h0, l0); fsplit(v1, h1, l1); fsplit(v2, h2, l2); fsplit(v3, h3, l3);
    long base = (long)node * 64 + f4 * 4;
    __nv_bfloat162 a2, b2;
    a2.x = h0; a2.y = h1; b2.x = h2; b2.y = h3;
    *(__nv_bfloat162*)(g_xah + base)     = a2;
    *(__nv_bfloat162*)(g_xah + base + 2) = b2;
    a2.x = l0; a2.y = l1; b2.x = l2; b2.y = l3;
    *(__nv_bfloat162*)(g_xal + base)     = a2;
    *(__nv_bfloat162*)(g_xal + base + 2) = b2;
}

// ================= GEMM1 (HMMA): [N,64] @ [64,512] -> x3 (relu+bias, bf16 split) ========
// ybase+y in {0,1}: A = x hi/lo,    bias b_fc     -> x1 (cols 0..255)
// ybase+y in {2,3}: A = xagg hi/lo, bias b_conv1  -> x2 (cols 256..511)
__global__ __launch_bounds__(256) void gemm1_mma(const float* __restrict__ b_fc,
                                                 const float* __restrict__ b_conv1,
                                                 int ybase, int n) {
    extern __shared__ char smem[];
    uint32_t sb = smem_u32(smem);
    int tid = threadIdx.x, wid = tid >> 5, lane = tid & 31;
    int bm0 = blockIdx.x * 128, bn0 = (blockIdx.y + ybase) * 128;
    bool isfc = bn0 < 256;
    const __nv_bfloat16* Ah = isfc ? g_xh : g_xah;
    const __nv_bfloat16* Al = isfc ? g_xl : g_xal;
    int wm = (wid >> 2) * 64, wn = (wid & 3) * 32;

    #pragma unroll
    for (int i = 0; i < 4; i++) {
        int t = tid + i * 256;
        int row = t >> 3, j = t & 7;
        long grow = bm0 + row;
        uint4 vh = make_uint4(0u, 0u, 0u, 0u), vl = vh;
        if (grow < n) {
            vh = ((const uint4*)(Ah + grow * 64))[j];
            vl = ((const uint4*)(Al + grow * 64))[j];
        }
        *(uint4*)(smem + G_AH + row * 144 + j * 16) = vh;
        *(uint4*)(smem + G_AL + row * 144 + j * 16) = vl;
        long rb = bn0 + row;
        *(uint4*)(smem + G_BH + row * 144 + j * 16) = ((const uint4*)(g_b1h + rb * 64))[j];
        *(uint4*)(smem + G_BL + row * 144 + j * 16) = ((const uint4*)(g_b1l + rb * 64))[j];
    }
    __syncthreads();

    int g = lane >> 3, r = lane & 7;
    uint32_t offA = (uint32_t)(((wm + (g & 1) * 8 + r) * LDS + (g >> 1) * 8) * 2);
    uint32_t offB = (uint32_t)(((wn + (g >> 1) * 8 + r) * LDS + (g & 1) * 8) * 2);

    float acc[4][4][4];
    #pragma unroll
    for (int mi = 0; mi < 4; mi++)
        #pragma unroll
        for (int nf = 0; nf < 4; nf++)
            #pragma unroll
            for (int q = 0; q < 4; q++) acc[mi][nf][q] = 0.f;

    chunk64<4>(sb, offA, offB, acc);

    int qrow = lane >> 2, qcol = (lane & 3) * 2;
    #pragma unroll
    for (int mi = 0; mi < 4; mi++) {
        int r0 = bm0 + wm + mi * 16 + qrow;
        int r1 = r0 + 8;
        #pragma unroll
        for (int nf = 0; nf < 4; nf++) {
            int col = bn0 + wn + nf * 8 + qcol;
            float* c = acc[mi][nf];
            float2 bb = isfc ? *(const float2*)(b_fc + col)
                             : *(const float2*)(b_conv1 + (col - 256));
            if (r0 < n) {
                float v0 = fmaxf(c[0] + bb.x, 0.f), v1 = fmaxf(c[1] + bb.y, 0.f);
                __nv_bfloat16 h0, l0, h1, l1;
                fsplit(v0, h0, l0); fsplit(v1, h1, l1);
                __nv_bfloat162 th; th.x = h0; th.y = h1;
                __nv_bfloat162 tl; tl.x = l0; tl.y = l1;
                *(__nv_bfloat162*)(g_x3h + (long)r0 * C2 + col) = th;
                *(__nv_bfloat162*)(g_x3l + (long)r0 * C2 + col) = tl;
            }
            if (r1 < n) {
                float v0 = fmaxf(c[2] + bb.x, 0.f), v1 = fmaxf(c[3] + bb.y, 0.f);
                __nv_bfloat16 h0, l0, h1, l1;
                fsplit(v0, h0, l0); fsplit(v1, h1, l1);
                __nv_bfloat162 th; th.x = h0; th.y = h1;
                __nv_bfloat162 tl; tl.x = l0; tl.y = l1;
                *(__nv_bfloat162*)(g_x3h + (long)r1 * C2 + col) = th;
                *(__nv_bfloat162*)(g_x3l + (long)r1 * C2 + col) = tl;
            }
        }
    }
}

// ================= GEMM2 (HMMA, cp.async double-buffered, 512 thr): [N,512] @ [512,256] ====
// y-block 0 (cols 0..127)  -> relu(+b_fc1) -> g_x7 (x5)
// y-block 1 (cols 128..255)-> raw fp32     -> g_xc2
__global__ __launch_bounds__(512) void gemm2_mma(const float* __restrict__ b_fc1, int n) {
    extern __shared__ char smem[];
    uint32_t sb = smem_u32(smem);
    int tid = threadIdx.x, wid = tid >> 5, lane = tid & 31;
    int bm0 = blockIdx.x * 128, bn0 = blockIdx.y * 128;
    bool isfc = (bn0 == 0);
    int wm = (wid >> 2) * 32, wn = (wid & 3) * 32;   // 16 warps: 4x4 of 32x32

    // per-thread load coordinates (2 quads per array)
    int rows[2], js[2];
    long garow[2];
    int apred[2];
    #pragma unroll
    for (int i = 0; i < 2; i++) {
        int t = tid + i * 512;
        rows[i] = t >> 3; js[i] = t & 7;
        long grow = bm0 + rows[i];
        apred[i] = grow < n;
        garow[i] = apred[i] ? grow : 0;
    }

    auto issue = [&](int c, int buf) {
        uint32_t base = sb + buf * G_BUF;
        int k0 = c * 64;
        #pragma unroll
        for (int i = 0; i < 2; i++) {
            int row = rows[i], j = js[i];
            uint32_t doff = row * 144 + j * 16;
            cpa(base + G_AH + doff, g_x3h + garow[i] * C2 + k0 + j * 8, apred[i]);
            cpa(base + G_AL + doff, g_x3l + garow[i] * C2 + k0 + j * 8, apred[i]);
            long rb = bn0 + row;
            cpa(base + G_BH + doff, g_b2h + rb * C2 + k0 + j * 8, 1);
            cpa(base + G_BL + doff, g_b2l + rb * C2 + k0 + j * 8, 1);
        }
        CP_COMMIT();
    };

    int g = lane >> 3, r = lane & 7;
    uint32_t offA = (uint32_t)(((wm + (g & 1) * 8 + r) * LDS + (g >> 1) * 8) * 2);
    uint32_t offB = (uint32_t)(((wn + (g >> 1) * 8 + r) * LDS + (g & 1) * 8) * 2);

    float acc[2][4][4];
    #pragma unroll
    for (int mi = 0; mi < 2; mi++)
        #pragma unroll
        for (int nf = 0; nf < 4; nf++)
            #pragma unroll
            for (int q = 0; q < 4; q++) acc[mi][nf][q] = 0.f;

    issue(0, 0);
    for (int c = 0; c < 8; c++) {
        if (c < 7) {
            issue(c + 1, (c + 1) & 1);
            CP_WAIT(1);
        } else {
            CP_WAIT(0);
        }
        __syncthreads();
        chunk64<2>(sb + (c & 1) * G_BUF, offA, offB, acc);
        __syncthreads();
    }

    int qrow = lane >> 2, qcol = (lane & 3) * 2;
    #pragma unroll
    for (int mi = 0; mi < 2; mi++) {
        int r0 = bm0 + wm + mi * 16 + qrow;
        int r1 = r0 + 8;
        #pragma unroll
        for (int nf = 0; nf < 4; nf++) {
            int col = wn + nf * 8 + qcol;     // 0..127 within slab
            float* c = acc[mi][nf];
            if (isfc) {
                float2 bb = *(const float2*)(b_fc1 + col);
                if (r0 < n) {
                    float2 o = make_float2(fmaxf(c[0] + bb.x, 0.f), fmaxf(c[1] + bb.y, 0.f));
                    *(float2*)(g_x7 + (long)r0 * OUTD + col) = o;
                }
                if (r1 < n) {
                    float2 o = make_float2(fmaxf(c[2] + bb.x, 0.f), fmaxf(c[3] + bb.y, 0.f));
                    *(float2*)(g_x7 + (long)r1 * OUTD + col) = o;
                }
            } else {
                if (r0 < n) *(float2*)(g_xc2 + (long)r0 * OUTD + col) = make_float2(c[0], c[1]);
                if (r1 < n) *(float2*)(g_xc2 + (long)r1 * OUTD + col) = make_float2(c[2], c[3]);
            }
        }
    }
}

// ---------- Fused aggregate conv2 + head: x7 in regs, dots inline, no x7 writeback ----------
__global__ __launch_bounds__(128) void agg2_head_kernel(
    const float* __restrict__ b_conv2, const float* __restrict__ w_fc2,
    const float* __restrict__ b_fc2, const float* __restrict__ w_conv3, int n)
{
    int node = blockIdx.x * 4 + (threadIdx.x >> 5);
    int f4 = threadIdx.x & 31;
    if (node >= n) return;
    int s = g_colptr[node], e = g_colptr[node + 1];
    float4 acc = make_float4(0.f, 0.f, 0.f, 0.f);
    for (int p = s; p < e; p++) {
        int r = g_erow[p];
        float w = g_ewt[p];
        float4 v = ((const float4*)g_xc2)[(long)r * 32 + f4];
        acc.x += w * v.x; acc.y += w * v.y; acc.z += w * v.z; acc.w += w * v.w;
    }
    float di = g_dis[node];
    float4 b = ((const float4*)b_conv2)[f4];
    float4 cur = ((const float4*)g_x7)[(long)node * 32 + f4];   // x5
    cur.x += fmaxf(acc.x * di + b.x, 0.f);
    cur.y += fmaxf(acc.y * di + b.y, 0.f);
    cur.z += fmaxf(acc.z * di + b.z, 0.f);
    cur.w += fmaxf(acc.w * di + b.w, 0.f);
    // head dots (x7 never stored)
    float4 wf = ((const float4*)w_fc2)[f4];
    float4 wc = ((const float4*)w_conv3)[f4];
    float d1 = cur.x * wf.x + cur.y * wf.y + cur.z * wf.z + cur.w * wf.w;
    float d2 = cur.x * wc.x + cur.y * wc.y + cur.z * wc.z + cur.w * wc.w;
    #pragma unroll
    for (int off = 16; off > 0; off >>= 1) {
        d1 += __shfl_down_sync(0xffffffffu, d1, off);
        d2 += __shfl_down_sync(0xffffffffu, d2, off);
    }
    if (f4 == 0) {
        g_pre[node] = d1 + b_fc2[0];
        g_xc3[node] = d2;
    }
}

// ---------------- Final aggregate conv3 + output ----------------
__global__ __launch_bounds__(256) void agg3_kernel(
    const float* __restrict__ b_conv3, float* __restrict__ out, int n)
{
    int gw = (blockIdx.x * blockDim.x + threadIdx.x) >> 5;
    int lane = threadIdx.x & 31;
    if (gw >= n) return;
    int s = g_colptr[gw], e = g_colptr[gw + 1];
    float acc = 0.f;
    for (int p = s + lane; p < e; p += 32)
        acc += g_ewt[p] * g_xc3[g_erow[p]];
    #pragma unroll
    for (int off = 16; off > 0; off >>= 1)
        acc += __shfl_down_sync(0xffffffffu, acc, off);
    if (lane == 0)
        out[gw] = g_pre[gw] + b_conv3[0] + g_dis[gw] * acc;
}

// ---------------- launch ----------------
extern "C" void kernel_launch(void* const* d_in, const int* in_sizes, int n_in,
                              void* d_out, int out_size)
{
    const float* x        = (const float*)d_in[0];
    const void*  edges    = d_in[1];
    const float* w_fc     = (const float*)d_in[2];
    const float* b_fc     = (const float*)d_in[3];
    const float* w_conv1  = (const float*)d_in[4];
    const float* b_conv1  = (const float*)d_in[5];
    const float* w_fc1    = (const float*)d_in[6];
    const float* b_fc1    = (const float*)d_in[7];
    const float* w_conv2  = (const float*)d_in[8];
    const float* b_conv2  = (const float*)d_in[9];
    const float* w_fc2    = (const float*)d_in[10];
    const float* b_fc2    = (const float*)d_in[11];
    const float* w_conv3  = (const float*)d_in[12];
    const float* b_conv3  = (const float*)d_in[13];
    float* out = (float*)d_out;

    int n = in_sizes[0] / INDIM;   // 50000
    int E = in_sizes[1] / 2;       // 800000
    int NB = (n + SCB - 1) / SCB;

    // lazily created side stream + events (host-side only; first call is the
    // uncaptured correctness run, so creation never happens during capture).
    static cudaStream_t s2 = nullptr;
    static cudaEvent_t evRoot = nullptr, evW = nullptr, ev2 = nullptr;
    static bool attrs_set = false;
    if (!s2) {
        cudaStreamCreateWithFlags(&s2, cudaStreamNonBlocking);
        cudaEventCreateWithFlags(&evRoot, cudaEventDisableTiming);
        cudaEventCreateWithFlags(&evW, cudaEventDisableTiming);
        cudaEventCreateWithFlags(&ev2, cudaEventDisableTiming);
    }
    if (!attrs_set) {
        cudaFuncSetAttribute(gemm1_mma, cudaFuncAttributeMaxDynamicSharedMemorySize, G1_SMEM);
        cudaFuncSetAttribute(gemm2_mma, cudaFuncAttributeMaxDynamicSharedMemorySize, G2_SMEM);
        attrs_set = true;
    }

    int mtiles = (n + 127) / 128;

    // fork side stream off the capture-origin (legacy) stream
    cudaEventRecord(evRoot, 0);
    cudaStreamWaitEvent(s2, evRoot, 0);

    // ---- side stream: input/weight conversions + fc half of gemm1 ----
    conv_x_kernel<<<(n * INDIM + 255) / 256, 256, 0, s2>>>(x, n * INDIM);
    conv_w1_kernel<<<(C2 * INDIM) / 256, 256, 0, s2>>>(w_fc, w_conv1);
    cudaEventRecord(evW, s2);                       // w1 split ready (needed by gemm1b)
    conv_w2_kernel<<<(256 * C2) / 256, 256, 0, s2>>>(w_fc1, w_conv2);
    dim3 g1a(mtiles, 2);
    gemm1_mma<<<g1a, 256, G1_SMEM, s2>>>(b_fc, b_conv1, 0, n);   // x1 half
    cudaEventRecord(ev2, s2);

    // ---- main stream: CSR build + aggx + conv half of gemm1 ----
    detect_kernel<<<1, 256>>>((const int*)edges, 4096);
    zero_deg_kernel<<<(n + 255) / 256, 256>>>(n);
    count_kernel<<<(E + 255) / 256, 256>>>(edges, E);
    scan_blocks_kernel<<<NB, SCB>>>(n);
    scan_sums_kernel<<<1, 1024>>>(NB);
    scan_add_kernel<<<NB, SCB>>>(n, E);
    fill_kernel<<<(E + 255) / 256, 256>>>(edges, E);
    aggx_kernel<<<(n + 7) / 8, 128>>>(x, n);

    cudaStreamWaitEvent(0, evW, 0);
    dim3 g1b(mtiles, 2);
    gemm1_mma<<<g1b, 256, G1_SMEM>>>(b_fc, b_conv1, 2, n);       // x2 half

    cudaStreamWaitEvent(0, ev2, 0);                 // join: x3 + w2 splits complete
    dim3 g2(mtiles, 2);
    gemm2_mma<<<g2, 512, G2_SMEM>>>(b_fc1, n);
    agg2_head_kernel<<<(n + 3) / 4, 128>>>(b_conv2, w_fc2, b_fc2, w_conv3, n);

    int blocks = (n * 32 + 255) / 256;
    agg3_kernel<<<blocks, 256>>>(b_conv3, out, n);
}

// round 10
// speedup vs baseline: 3.7680x; 1.3097x over previous
#include <cuda_runtime.h>
#include <cuda_fp16.h>
#include <cstdint>

// Problem constants (fixed by the dataset)
#define NN    50000
#define EE    800000
#define INDIM 64
#define HID   256
#define OUTD  128
#define C2    512   // 2*HID

// ---------------- device scratch (static: no allocation allowed) ----------------
__device__ __half g_x16 [NN * INDIM];   // x (fp16)
__device__ __half g_xa16[NN * INDIM];   // A_norm x (fp16)
__device__ __half g_x3f [NN * C2];      // x3 (fp16)
__device__ __half g_b1h[C2 * INDIM];    // B1[n][k] = concat(w_fc,w_conv1)^T fp16 hi
__device__ __half g_b1l[C2 * INDIM];    //                                  fp16 lo
__device__ __half g_b2h[256 * C2];      // B2[n][k] = concat(w_fc1,w_conv2)^T hi
__device__ __half g_b2l[256 * C2];
__device__ float g_xc2[NN * OUTD];   // x3 @ w_conv2 (raw, fp32)
__device__ float g_x7 [NN * OUTD];   // x5 (fc1 branch)
__device__ float g_xc3[NN];
__device__ float g_pre[NN];
__device__ float g_dis[NN];
__device__ int   g_deg[NN];
__device__ int   g_colptr[NN + 1];
__device__ int   g_cursor[NN];
__device__ int   g_erow[EE];
__device__ float g_ewt [EE];
__device__ int   g_bsum[1024];
__device__ int   g_is64;

// ---------------- mma.sync helpers (sm_80-era PTX: valid on plain sm_103) ----------------
__device__ __forceinline__ uint32_t smem_u32(const void* p) {
    uint32_t a;
    asm("{ .reg .u64 t; cvta.to.shared.u64 t, %1; cvt.u32.u64 %0, t; }" : "=r"(a) : "l"(p));
    return a;
}
__device__ __forceinline__ void ldsm4(uint32_t* d, uint32_t addr) {
    asm volatile("ldmatrix.sync.aligned.m8n8.x4.shared.b16 {%0,%1,%2,%3}, [%4];"
                 : "=r"(d[0]), "=r"(d[1]), "=r"(d[2]), "=r"(d[3]) : "r"(addr));
}
__device__ __forceinline__ void mma_f16(float* c, const uint32_t* a, uint32_t b0, uint32_t b1) {
    asm volatile(
        "mma.sync.aligned.m16n8k16.row.col.f32.f16.f16.f32 "
        "{%0,%1,%2,%3}, {%4,%5,%6,%7}, {%8,%9}, {%0,%1,%2,%3};"
        : "+f"(c[0]), "+f"(c[1]), "+f"(c[2]), "+f"(c[3])
        : "r"(a[0]), "r"(a[1]), "r"(a[2]), "r"(a[3]), "r"(b0), "r"(b1));
}
__device__ __forceinline__ void fsplit16(float v, __half& h, __half& l) {
    h = __float2half(v);
    l = __float2half(v - __half2float(h));
}
// cp.async 16B with zero-fill predicate (src-size 0 -> zeros)
__device__ __forceinline__ void cpa(uint32_t dst, const void* src, int pred) {
    asm volatile("cp.async.cg.shared.global [%0], [%1], 16, %2;"
                 :: "r"(dst), "l"(src), "r"(pred ? 16 : 0) : "memory");
}
#define CP_COMMIT() asm volatile("cp.async.commit_group;" ::: "memory")
#define CP_WAIT(N)  asm volatile("cp.async.wait_group %0;" :: "n"(N) : "memory")

// SMEM layout: 128 rows x 64 fp16, stride 72 elems (144B rows, conflict-free ldmatrix)
#define LDS    72
#define TILEB  (128 * LDS * 2)     // 18432 bytes
#define G_A    0
#define G_BH   TILEB
#define G_BL   (2 * TILEB)
#define G_BUF  (3 * TILEB)         // 55296 per stage
#define G1_SMEM G_BUF
#define G2_SMEM (2 * G_BUF)        // 110592 (double buffered)

// One K=64 chunk: 2-product fp16 GEMM (A single, B hi/lo). MF = #m-frags per warp.
template <int MF>
__device__ __forceinline__ void chunk64(uint32_t base, uint32_t offA, uint32_t offB,
                                        float acc[][4][4]) {
    #pragma unroll
    for (int ks = 0; ks < 4; ks++) {
        uint32_t ka = ks * 32;                      // k16 step = 16 fp16 = 32 bytes
        uint32_t a[MF][4], bh[4][2], bl[4][2];
        #pragma unroll
        for (int mi = 0; mi < MF; mi++) ldsm4(a[mi], base + G_A + offA + mi * 2304 + ka);
        #pragma unroll
        for (int nj = 0; nj < 2; nj++) {
            uint32_t t[4];
            ldsm4(t, base + G_BH + offB + nj * 2304 + ka);
            bh[nj * 2][0] = t[0]; bh[nj * 2][1] = t[1];
            bh[nj * 2 + 1][0] = t[2]; bh[nj * 2 + 1][1] = t[3];
            ldsm4(t, base + G_BL + offB + nj * 2304 + ka);
            bl[nj * 2][0] = t[0]; bl[nj * 2][1] = t[1];
            bl[nj * 2 + 1][0] = t[2]; bl[nj * 2 + 1][1] = t[3];
        }
        #pragma unroll
        for (int mi = 0; mi < MF; mi++)
            #pragma unroll
            for (int nf = 0; nf < 4; nf++) {
                mma_f16(acc[mi][nf], a[mi], bh[nf][0], bh[nf][1]);
                mma_f16(acc[mi][nf], a[mi], bl[nf][0], bl[nf][1]);
            }
    }
}

// ---------------- edge dtype handling ----------------
__global__ void detect_kernel(const int* __restrict__ p, int nwords) {
    __shared__ int any;
    if (threadIdx.x == 0) any = 0;
    __syncthreads();
    int v = 0;
    for (int i = threadIdx.x; i < nwords; i += blockDim.x)
        if (i & 1) v |= p[i];
    if (v) atomicOr(&any, 1);
    __syncthreads();
    if (threadIdx.x == 0) g_is64 = (any == 0) ? 1 : 0;
}
__device__ __forceinline__ int edge_val(const void* e, long idx) {
    if (g_is64) return (int)((const long long*)e)[idx];
    return ((const int*)e)[idx];
}

// ---------------- CSR build ----------------
__global__ void zero_deg_kernel(int n) {
    int i = blockIdx.x * blockDim.x + threadIdx.x;
    if (i < n) g_deg[i] = 0;
}
__global__ void count_kernel(const void* __restrict__ edges, int E) {
    int e = blockIdx.x * blockDim.x + threadIdx.x;
    if (e < E) atomicAdd(&g_deg[edge_val(edges, (long)E + e)], 1);
}
#define SCB 512
__global__ void scan_blocks_kernel(int n) {
    __shared__ int sm[SCB];
    int i = blockIdx.x * SCB + threadIdx.x;
    int v = (i < n) ? g_deg[i] : 0;
    sm[threadIdx.x] = v;
    __syncthreads();
    for (int off = 1; off < SCB; off <<= 1) {
        int t = 0;
        if ((int)threadIdx.x >= off) t = sm[threadIdx.x - off];
        __syncthreads();
        sm[threadIdx.x] += t;
        __syncthreads();
    }
    if (i < n) g_colptr[i] = sm[threadIdx.x] - v;
    if (threadIdx.x == SCB - 1) g_bsum[blockIdx.x] = sm[SCB - 1];
}
__global__ void scan_sums_kernel(int nb) {
    __shared__ int sm[1024];
    int v = (threadIdx.x < (unsigned)nb) ? g_bsum[threadIdx.x] : 0;
    sm[threadIdx.x] = v;
    __syncthreads();
    for (int off = 1; off < 1024; off <<= 1) {
        int t = 0;
        if ((int)threadIdx.x >= off) t = sm[threadIdx.x - off];
        __syncthreads();
        sm[threadIdx.x] += t;
        __syncthreads();
    }
    if (threadIdx.x < (unsigned)nb) g_bsum[threadIdx.x] = sm[threadIdx.x] - v;
}
__global__ void scan_add_kernel(int n, int Etot) {
    int i = blockIdx.x * SCB + threadIdx.x;
    if (i < n) {
        int v = g_colptr[i] + g_bsum[blockIdx.x];
        g_colptr[i] = v;
        g_cursor[i] = v;
        int d = g_deg[i];
        g_dis[i] = (d > 0) ? rsqrtf((float)d) : 0.0f;
    }
    if (i == 0) g_colptr[n] = Etot;
}
__global__ void fill_kernel(const void* __restrict__ edges, int E) {
    int e = blockIdx.x * blockDim.x + threadIdx.x;
    if (e < E) {
        int r = edge_val(edges, e);
        int c = edge_val(edges, (long)E + e);
        int pos = atomicAdd(&g_cursor[c], 1);
        g_erow[pos] = r;
        g_ewt[pos]  = g_dis[r];
    }
}

// ---------------- conversions ----------------
__global__ void conv_x_kernel(const float* __restrict__ x, int total) {
    int i = blockIdx.x * blockDim.x + threadIdx.x;
    if (i < total) g_x16[i] = __float2half(x[i]);
}
// B1[n][k] = (n<256 ? w_fc[k][n] : w_conv1[k][n-256]),  [512 x 64], fp16 hi/lo
__global__ void conv_w1_kernel(const float* __restrict__ w_fc, const float* __restrict__ w_conv1) {
    int i = blockIdx.x * blockDim.x + threadIdx.x;   // 512*64
    int nidx = i >> 6, k = i & 63;
    float v = (nidx < 256) ? w_fc[k * 256 + nidx] : w_conv1[k * 256 + (nidx - 256)];
    fsplit16(v, g_b1h[i], g_b1l[i]);
}
// B2[n][k] = (n<128 ? w_fc1[k][n] : w_conv2[k][n-128]),  [256 x 512], fp16 hi/lo
__global__ void conv_w2_kernel(const float* __restrict__ w_fc1, const float* __restrict__ w_conv2) {
    int i = blockIdx.x * blockDim.x + threadIdx.x;   // 256*512
    int nidx = i >> 9, k = i & 511;
    float v = (nidx < 128) ? w_fc1[k * 128 + nidx] : w_conv2[k * 128 + (nidx - 128)];
    fsplit16(v, g_b2h[i], g_b2l[i]);
}

// ---------------- Aggregate X (propagate-then-transform for conv1), 2-way unrolled ----------------
__global__ __launch_bounds__(128) void aggx_kernel(const float* __restrict__ x, int n) {
    int node = blockIdx.x * 8 + (threadIdx.x >> 4);
    int f4 = threadIdx.x & 15;
    if (node >= n) return;
    int s = g_colptr[node], e = g_colptr[node + 1];
    float4 acc = make_float4(0.f, 0.f, 0.f, 0.f);
    float4 acc2 = make_float4(0.f, 0.f, 0.f, 0.f);
    int p = s;
    for (; p + 2 <= e; p += 2) {
        int r0 = g_erow[p], r1 = g_erow[p + 1];
        float w0 = g_ewt[p], w1 = g_ewt[p + 1];
        float4 v0 = ((const float4*)x)[(long)r0 * 16 + f4];
        float4 v1 = ((const float4*)x)[(long)r1 * 16 + f4];
        acc.x += w0 * v0.x; acc.y += w0 * v0.y; acc.z += w0 * v0.z; acc.w += w0 * v0.w;
        acc2.x += w1 * v1.x; acc2.y += w1 * v1.y; acc2.z += w1 * v1.z; acc2.w += w1 * v1.w;
    }
    if (p < e) {
        int r0 = g_erow[p];
        float w0 = g_ewt[p];
        float4 v0 = ((const float4*)x)[(long)r0 * 16 + f4];
        acc.x += w0 * v0.x; acc.y += w0 * v0.y; acc.z += w0 * v0.z; acc.w += w0 * v0.w;
    }
    acc.x += acc2.x; acc.y += acc2.y; acc.z += acc2.z; acc.w += acc2.w;
    float di = g_dis[node];
    __half2 h01, h23;
    h01.x = __float2half(acc.x * di); h01.y = __float2half(acc.y * di);
    h23.x = __float2half(acc.z * di); h23.y = __float2half(acc.w * di);
    long base = (long)node * 64 + f4 * 4;
    *(__half2*)(g_xa16 + base)     = h01;
    *(__half2*)(g_xa16 + base + 2) = h23;
}

// ================= GEMM1 (HMMA fp16): [N,64] @ [64,512] -> x3 fp16 (relu+bias) ========
// ybase+y in {0,1}: A = x16,  bias b_fc     -> x1 (cols 0..255)
// ybase+y in {2,3}: A = xa16, bias b_conv1  -> x2 (cols 256..511)
__global__ __launch_bounds__(256) void gemm1_mma(const float* __restrict__ b_fc,
                                                 const float* __restrict__ b_conv1,
                                                 int ybase, int n) {
    extern __shared__ char smem[];
    uint32_t sb = smem_u32(smem);
    int tid = threadIdx.x, wid = tid >> 5, lane = tid & 31;
    int bm0 = blockIdx.x * 128, bn0 = (blockIdx.y + ybase) * 128;
    bool isfc = bn0 < 256;
    const __half* A = isfc ? g_x16 : g_xa16;
    int wm = (wid >> 2) * 64, wn = (wid & 3) * 32;

    #pragma unroll
    for (int i = 0; i < 4; i++) {
        int t = tid + i * 256;
        int row = t >> 3, j = t & 7;
        long grow = bm0 + row;
        uint4 va = make_uint4(0u, 0u, 0u, 0u);
        if (grow < n) va = ((const uint4*)(A + grow * 64))[j];
        *(uint4*)(smem + G_A + row * 144 + j * 16) = va;
        long rb = bn0 + row;
        *(uint4*)(smem + G_BH + row * 144 + j * 16) = ((const uint4*)(g_b1h + rb * 64))[j];
        *(uint4*)(smem + G_BL + row * 144 + j * 16) = ((const uint4*)(g_b1l + rb * 64))[j];
    }
    __syncthreads();

    int g = lane >> 3, r = lane & 7;
    uint32_t offA = (uint32_t)(((wm + (g & 1) * 8 + r) * LDS + (g >> 1) * 8) * 2);
    uint32_t offB = (uint32_t)(((wn + (g >> 1) * 8 + r) * LDS + (g & 1) * 8) * 2);

    float acc[4][4][4];
    #pragma unroll
    for (int mi = 0; mi < 4; mi++)
        #pragma unroll
        for (int nf = 0; nf < 4; nf++)
            #pragma unroll
            for (int q = 0; q < 4; q++) acc[mi][nf][q] = 0.f;

    chunk64<4>(sb, offA, offB, acc);

    int qrow = lane >> 2, qcol = (lane & 3) * 2;
    #pragma unroll
    for (int mi = 0; mi < 4; mi++) {
        int r0 = bm0 + wm + mi * 16 + qrow;
        int r1 = r0 + 8;
        #pragma unroll
        for (int nf = 0; nf < 4; nf++) {
            int col = bn0 + wn + nf * 8 + qcol;
            float* c = acc[mi][nf];
            float2 bb = isfc ? *(const float2*)(b_fc + col)
                             : *(const float2*)(b_conv1 + (col - 256));
            if (r0 < n) {
                __half2 o;
                o.x = __float2half(fmaxf(c[0] + bb.x, 0.f));
                o.y = __float2half(fmaxf(c[1] + bb.y, 0.f));
                *(__half2*)(g_x3f + (long)r0 * C2 + col) = o;
            }
            if (r1 < n) {
                __half2 o;
                o.x = __float2half(fmaxf(c[2] + bb.x, 0.f));
                o.y = __float2half(fmaxf(c[3] + bb.y, 0.f));
                *(__half2*)(g_x3f + (long)r1 * C2 + col) = o;
            }
        }
    }
}

// ================= GEMM2 (HMMA fp16, cp.async double-buffered, 512 thr): [N,512]@[512,256] ====
// y-block 0 (cols 0..127)  -> relu(+b_fc1) -> g_x7 (x5)
// y-block 1 (cols 128..255)-> raw fp32     -> g_xc2
__global__ __launch_bounds__(512) void gemm2_mma(const float* __restrict__ b_fc1, int n) {
    extern __shared__ char smem[];
    uint32_t sb = smem_u32(smem);
    int tid = threadIdx.x, wid = tid >> 5, lane = tid & 31;
    int bm0 = blockIdx.x * 128, bn0 = blockIdx.y * 128;
    bool isfc = (bn0 == 0);
    int wm = (wid >> 2) * 32, wn = (wid & 3) * 32;   // 16 warps: 4x4 of 32x32

    // per-thread load coordinates: 3072 quads/stage over 512 threads = 6 cpa each
    int rows[2], js[2];
    long garow[2];
    int apred[2];
    #pragma unroll
    for (int i = 0; i < 2; i++) {
        int t = tid + i * 512;
        rows[i] = t >> 3; js[i] = t & 7;
        long grow = bm0 + rows[i];
        apred[i] = grow < n;
        garow[i] = apred[i] ? grow : 0;
    }

    auto issue = [&](int c, int buf) {
        uint32_t base = sb + buf * G_BUF;
        int k0 = c * 64;
        #pragma unroll
        for (int i = 0; i < 2; i++) {
            int row = rows[i], j = js[i];
            uint32_t doff = row * 144 + j * 16;
            cpa(base + G_A + doff, g_x3f + garow[i] * C2 + k0 + j * 8, apred[i]);
            long rb = bn0 + row;
            cpa(base + G_BH + doff, g_b2h + rb * C2 + k0 + j * 8, 1);
            cpa(base + G_BL + doff, g_b2l + rb * C2 + k0 + j * 8, 1);
        }
        CP_COMMIT();
    };

    int g = lane >> 3, r = lane & 7;
    uint32_t offA = (uint32_t)(((wm + (g & 1) * 8 + r) * LDS + (g >> 1) * 8) * 2);
    uint32_t offB = (uint32_t)(((wn + (g >> 1) * 8 + r) * LDS + (g & 1) * 8) * 2);

    float acc[2][4][4];
    #pragma unroll
    for (int mi = 0; mi < 2; mi++)
        #pragma unroll
        for (int nf = 0; nf < 4; nf++)
            #pragma unroll
            for (int q = 0; q < 4; q++) acc[mi][nf][q] = 0.f;

    issue(0, 0);
    for (int c = 0; c < 8; c++) {
        if (c < 7) {
            issue(c + 1, (c + 1) & 1);
            CP_WAIT(1);
        } else {
            CP_WAIT(0);
        }
        __syncthreads();
        chunk64<2>(sb + (c & 1) * G_BUF, offA, offB, acc);
        __syncthreads();
    }

    int qrow = lane >> 2, qcol = (lane & 3) * 2;
    #pragma unroll
    for (int mi = 0; mi < 2; mi++) {
        int r0 = bm0 + wm + mi * 16 + qrow;
        int r1 = r0 + 8;
        #pragma unroll
        for (int nf = 0; nf < 4; nf++) {
            int col = wn + nf * 8 + qcol;     // 0..127 within slab
            float* c = acc[mi][nf];
            if (isfc) {
                float2 bb = *(const float2*)(b_fc1 + col);
                if (r0 < n) {
                    float2 o = make_float2(fmaxf(c[0] + bb.x, 0.f), fmaxf(c[1] + bb.y, 0.f));
                    *(float2*)(g_x7 + (long)r0 * OUTD + col) = o;
                }
                if (r1 < n) {
                    float2 o = make_float2(fmaxf(c[2] + bb.x, 0.f), fmaxf(c[3] + bb.y, 0.f));
                    *(float2*)(g_x7 + (long)r1 * OUTD + col) = o;
                }
            } else {
                if (r0 < n) *(float2*)(g_xc2 + (long)r0 * OUTD + col) = make_float2(c[0], c[1]);
                if (r1 < n) *(float2*)(g_xc2 + (long)r1 * OUTD + col) = make_float2(c[2], c[3]);
            }
        }
    }
}

// ---------- Fused aggregate conv2 + head (2-way unrolled gather) ----------
__global__ __launch_bounds__(128) void agg2_head_kernel(
    const float* __restrict__ b_conv2, const float* __restrict__ w_fc2,
    const float* __restrict__ b_fc2, const float* __restrict__ w_conv3, int n)
{
    int node = blockIdx.x * 4 + (threadIdx.x >> 5);
    int f4 = threadIdx.x & 31;
    if (node >= n) return;
    int s = g_colptr[node], e = g_colptr[node + 1];
    float4 acc = make_float4(0.f, 0.f, 0.f, 0.f);
    float4 acc2 = make_float4(0.f, 0.f, 0.f, 0.f);
    int p = s;
    for (; p + 2 <= e; p += 2) {
        int r0 = g_erow[p], r1 = g_erow[p + 1];
        float w0 = g_ewt[p], w1 = g_ewt[p + 1];
        float4 v0 = ((const float4*)g_xc2)[(long)r0 * 32 + f4];
        float4 v1 = ((const float4*)g_xc2)[(long)r1 * 32 + f4];
        acc.x += w0 * v0.x; acc.y += w0 * v0.y; acc.z += w0 * v0.z; acc.w += w0 * v0.w;
        acc2.x += w1 * v1.x; acc2.y += w1 * v1.y; acc2.z += w1 * v1.z; acc2.w += w1 * v1.w;
    }
    if (p < e) {
        int r0 = g_erow[p];
        float w0 = g_ewt[p];
        float4 v0 = ((const float4*)g_xc2)[(long)r0 * 32 + f4];
        acc.x += w0 * v0.x; acc.y += w0 * v0.y; acc.z += w0 * v0.z; acc.w += w0 * v0.w;
    }
    acc.x += acc2.x; acc.y += acc2.y; acc.z += acc2.z; acc.w += acc2.w;
    float di = g_dis[node];
    float4 b = ((const float4*)b_conv2)[f4];
    float4 cur = ((const float4*)g_x7)[(long)node * 32 + f4];   // x5
    cur.x += fmaxf(acc.x * di + b.x, 0.f);
    cur.y += fmaxf(acc.y * di + b.y, 0.f);
    cur.z += fmaxf(acc.z * di + b.z, 0.f);
    cur.w += fmaxf(acc.w * di + b.w, 0.f);
    // head dots (x7 never stored)
    float4 wf = ((const float4*)w_fc2)[f4];
    float4 wc = ((const float4*)w_conv3)[f4];
    float d1 = cur.x * wf.x + cur.y * wf.y + cur.z * wf.z + cur.w * wf.w;
    float d2 = cur.x * wc.x + cur.y * wc.y + cur.z * wc.z + cur.w * wc.w;
    #pragma unroll
    for (int off = 16; off > 0; off >>= 1) {
        d1 += __shfl_down_sync(0xffffffffu, d1, off);
        d2 += __shfl_down_sync(0xffffffffu, d2, off);
    }
    if (f4 == 0) {
        g_pre[node] = d1 + b_fc2[0];
        g_xc3[node] = d2;
    }
}

// ---------------- Final aggregate conv3 + output ----------------
__global__ __launch_bounds__(256) void agg3_kernel(
    const float* __restrict__ b_conv3, float* __restrict__ out, int n)
{
    int gw = (blockIdx.x * blockDim.x + threadIdx.x) >> 5;
    int lane = threadIdx.x & 31;
    if (gw >= n) return;
    int s = g_colptr[gw], e = g_colptr[gw + 1];
    float acc = 0.f;
    for (int p = s + lane; p < e; p += 32)
        acc += g_ewt[p] * g_xc3[g_erow[p]];
    #pragma unroll
    for (int off = 16; off > 0; off >>= 1)
        acc += __shfl_down_sync(0xffffffffu, acc, off);
    if (lane == 0)
        out[gw] = g_pre[gw] + b_conv3[0] + g_dis[gw] * acc;
}

// ---------------- launch ----------------
extern "C" void kernel_launch(void* const* d_in, const int* in_sizes, int n_in,
                              void* d_out, int out_size)
{
    const float* x        = (const float*)d_in[0];
    const void*  edges    = d_in[1];
    const float* w_fc     = (const float*)d_in[2];
    const float* b_fc     = (const float*)d_in[3];
    const float* w_conv1  = (const float*)d_in[4];
    const float* b_conv1  = (const float*)d_in[5];
    const float* w_fc1    = (const float*)d_in[6];
    const float* b_fc1    = (const float*)d_in[7];
    const float* w_conv2  = (const float*)d_in[8];
    const float* b_conv2  = (const float*)d_in[9];
    const float* w_fc2    = (const float*)d_in[10];
    const float* b_fc2    = (const float*)d_in[11];
    const float* w_conv3  = (const float*)d_in[12];
    const float* b_conv3  = (const float*)d_in[13];
    float* out = (float*)d_out;

    int n = in_sizes[0] / INDIM;   // 50000
    int E = in_sizes[1] / 2;       // 800000
    int NB = (n + SCB - 1) / SCB;

    // lazily created side stream + events (host-side only; first call is the
    // uncaptured correctness run, so creation never happens during capture).
    static cudaStream_t s2 = nullptr;
    static cudaEvent_t evRoot = nullptr, evW = nullptr, ev2 = nullptr;
    static bool attrs_set = false;
    if (!s2) {
        cudaStreamCreateWithFlags(&s2, cudaStreamNonBlocking);
        cudaEventCreateWithFlags(&evRoot, cudaEventDisableTiming);
        cudaEventCreateWithFlags(&evW, cudaEventDisableTiming);
        cudaEventCreateWithFlags(&ev2, cudaEventDisableTiming);
    }
    if (!attrs_set) {
        cudaFuncSetAttribute(gemm1_mma, cudaFuncAttributeMaxDynamicSharedMemorySize, G1_SMEM);
        cudaFuncSetAttribute(gemm2_mma, cudaFuncAttributeMaxDynamicSharedMemorySize, G2_SMEM);
        attrs_set = true;
    }

    int mtiles = (n + 127) / 128;

    // fork side stream off the capture-origin (legacy) stream
    cudaEventRecord(evRoot, 0);
    cudaStreamWaitEvent(s2, evRoot, 0);

    // ---- side stream: input/weight conversions + fc half of gemm1 ----
    conv_x_kernel<<<(n * INDIM + 255) / 256, 256, 0, s2>>>(x, n * INDIM);
    conv_w1_kernel<<<(C2 * INDIM) / 256, 256, 0, s2>>>(w_fc, w_conv1);
    cudaEventRecord(evW, s2);                       // w1 split ready (needed by gemm1b)
    conv_w2_kernel<<<(256 * C2) / 256, 256, 0, s2>>>(w_fc1, w_conv2);
    dim3 g1a(mtiles, 2);
    gemm1_mma<<<g1a, 256, G1_SMEM, s2>>>(b_fc, b_conv1, 0, n);   // x1 half
    cudaEventRecord(ev2, s2);

    // ---- main stream: CSR build + aggx + conv half of gemm1 ----
    detect_kernel<<<1, 256>>>((const int*)edges, 4096);
    zero_deg_kernel<<<(n + 255) / 256, 256>>>(n);
    count_kernel<<<(E + 255) / 256, 256>>>(edges, E);
    scan_blocks_kernel<<<NB, SCB>>>(n);
    scan_sums_kernel<<<1, 1024>>>(NB);
    scan_add_kernel<<<NB, SCB>>>(n, E);
    fill_kernel<<<(E + 255) / 256, 256>>>(edges, E);
    aggx_kernel<<<(n + 7) / 8, 128>>>(x, n);

    cudaStreamWaitEvent(0, evW, 0);
    dim3 g1b(mtiles, 2);
    gemm1_mma<<<g1b, 256, G1_SMEM>>>(b_fc, b_conv1, 2, n);       // x2 half

    cudaStreamWaitEvent(0, ev2, 0);                 // join: x3 + w2 splits complete
    dim3 g2(mtiles, 2);
    gemm2_mma<<<g2, 512, G2_SMEM>>>(b_fc1, n);
    agg2_head_kernel<<<(n + 3) / 4, 128>>>(b_conv2, w_fc2, b_fc2, w_conv3, n);

    int blocks = (n * 32 + 255) / 256;
    agg3_kernel<<<blocks, 256>>>(b_conv3, out, n);
}